// round 9
// baseline (speedup 1.0000x reference)
#include <cuda_runtime.h>
#include <cstddef>

#define NEG_INFF (-9.0e15f)
#define BN_EPS 1e-5f

typedef unsigned long long u64;

__device__ __forceinline__ void fma2(u64 &d, u64 a, u64 b) {
    asm("fma.rn.f32x2 %0, %1, %2, %0;" : "+l"(d) : "l"(a), "l"(b));
}
__device__ __forceinline__ void up2(u64 v, float &lo, float &hi) {
    asm("mov.b64 {%0,%1}, %2;" : "=f"(lo), "=f"(hi) : "l"(v));
}

// ---------------- device-global weight scratch (allocation-free) ----------------
// g_Wqkv3[g][c][96]: head-group g (4 heads), channel c, 96 cols = {q:32 | k:32 | v:32}
__device__ float g_Wqkv3[4 * 128 * 96];
// g_WcT[c][o] = conv_w[o][c]
__device__ float g_WcT[256 * 256];

__global__ void prep_kernel(const float* __restrict__ Wq, const float* __restrict__ Wk,
                            const float* __restrict__ Wv, const float* __restrict__ convw) {
    int i = blockIdx.x * blockDim.x + threadIdx.x;
    if (i < 4 * 128 * 96) {
        int g = i / (128 * 96);
        int r = i - g * (128 * 96);
        int c = r / 96, col = r - c * 96;
        int part = col >> 5;
        int o = col & 31;
        int gc = g * 32 + o;
        int h = gc >> 3, e = gc & 7;
        const float* W = (part == 0) ? Wq : (part == 1 ? Wk : Wv);
        g_Wqkv3[i] = W[h * 1024 + c * 8 + e];
    } else {
        int j = i - 4 * 128 * 96;
        if (j < 256 * 256) {
            int c = j >> 8, o = j & 255;
            g_WcT[j] = convw[o * 256 + c];
        }
    }
}

// ---------------- smem layout (floats) ----------------
// XP/AP: token-paired x: [8 tt][9 slots][130 float2] ; slot s<8 = tokens (2s,2s+1), s=8 = token16 duplicated
#define PSTR 260
#define XP_OFF   0                       // 8*9*260 = 18720
#define AP_OFF   18720                   // 18720 -> ends 37440
#define SCR_OFF  37440
#define QSTR 36
#define QS_OFF   (SCR_OFF)               // qs[136][36]
#define KS_OFF   (SCR_OFF + 4896)
#define VS_OFF   (SCR_OFF + 9792)
#define MB_OFF   (SCR_OFF + 14688)       // mask[4][289]
#define WS_OFF   (SCR_OFF)               // union: duplicated weight tiles (<=12288 floats)
#define YS_OFF   (SCR_OFF)               // union: Ys[64][137]
#define BNS_OFF  53284
#define BNB_OFF  53540
#define SMEM_FLOATS 53796
#define SMEM_BYTES  (SMEM_FLOATS * 4)    // 215184

extern __shared__ float sm[];

__global__ void __launch_bounds__(256, 1)
gab_kernel(const float* __restrict__ x, const float* __restrict__ adj,
           const float* __restrict__ adj2,
           const float* __restrict__ bng, const float* __restrict__ bnbv,
           const float* __restrict__ bnm, const float* __restrict__ bnv,
           float* __restrict__ out) {
    const int b  = blockIdx.x >> 6;
    const int tb = blockIdx.x & 63;
    const int t0 = tb * 8;
    const int tid  = threadIdx.x;
    const int lane = tid & 31;
    const int wid  = tid >> 5;
    const int o32  = tid & 31;
    const int tt   = tid >> 5;

    // ---- Phase A: load X tile into token-paired layout XP ----
    {
        const float* xb = x + (size_t)b * 128 * 8704 + (size_t)t0 * 17;
        for (int d4 = wid; d4 < 32; d4 += 8) {
            const float* s0 = xb + (size_t)(d4 * 4 + 0) * 8704;
            const float* s1 = xb + (size_t)(d4 * 4 + 1) * 8704;
            const float* s2 = xb + (size_t)(d4 * 4 + 2) * 8704;
            const float* s3 = xb + (size_t)(d4 * 4 + 3) * 8704;
            for (int tok = lane; tok < 136; tok += 32) {
                float v0 = s0[tok], v1 = s1[tok], v2 = s2[tok], v3 = s3[tok];
                int tta = tok / 17;
                int loc = tok - tta * 17;
                int s   = loc >> 1, par = loc & 1;
                float* dst = sm + XP_OFF + (tta * 9 + s) * PSTR + par + d4 * 8;
                dst[0] = v0; dst[2] = v1; dst[4] = v2; dst[6] = v3;
                if (loc == 16) {  // duplicate token 16 into .y lane
                    dst[1] = v0; dst[3] = v1; dst[5] = v2; dst[7] = v3;
                }
            }
        }
    }
    // ---- BN fold ----
    {
        float sc = bng[tid] * rsqrtf(bnv[tid] + BN_EPS);
        sm[BNS_OFF + tid] = sc;
        sm[BNB_OFF + tid] = bnbv[tid] - bnm[tid] * sc;
    }
    __syncthreads();

    const float inv_s = 0.3535533905932738f;   // 1/sqrt(8)

    // ---- Phase B: 4 head-groups of 4 heads: packed QKV GEMM + attention ----
    for (int g = 0; g < 4; ++g) {
        u64 aq2[9], ak2[9], av2[9];
#pragma unroll
        for (int s = 0; s < 9; ++s) { aq2[s] = 0ull; ak2[s] = 0ull; av2[s] = 0ull; }

        // two c-halves; stage [64 c][96 cols] duplicated as float2 = 12288 floats
        for (int h = 0; h < 2; ++h) {
            {
                const float* src = g_Wqkv3 + g * 12288 + h * 6144;
                float2* dst = reinterpret_cast<float2*>(sm + WS_OFF);
#pragma unroll
                for (int j = 0; j < 24; ++j) {
                    float w = __ldg(src + tid + j * 256);
                    dst[tid + j * 256] = make_float2(w, w);
                }
                if (h == 0) {   // masks for this group (region beyond WS)
                    for (int idx = tid; idx < 4 * 289; idx += 256) {
                        int hl = idx / 289, r = idx - hl * 289;
                        int n = r / 17, m = r - n * 17;
                        int hh = g * 4 + hl;
                        float a = 0.5f * (adj[n * 17 + m] + adj[m * 17 + n])
                                + 0.5f * (adj2[hh * 289 + n * 17 + m] + adj2[hh * 289 + m * 17 + n]);
                        sm[MB_OFF + idx] = (a > 0.0f) ? 0.0f : NEG_INFF;
                    }
                }
            }
            __syncthreads();
            const float* xbase = sm + XP_OFF + tt * 9 * PSTR + h * 128;
            for (int c4 = 0; c4 < 16; ++c4) {
                u64 wq[4], wk[4], wv[4];
#pragma unroll
                for (int k = 0; k < 4; ++k) {
                    const u64* wrow = reinterpret_cast<const u64*>(sm + WS_OFF) + (c4 * 4 + k) * 96;
                    wq[k] = wrow[o32];
                    wk[k] = wrow[o32 + 32];
                    wv[k] = wrow[o32 + 64];
                }
#pragma unroll
                for (int s = 0; s < 9; ++s) {
                    const ulonglong2* xr = reinterpret_cast<const ulonglong2*>(xbase + s * PSTR + c4 * 8);
                    ulonglong2 x01 = xr[0];
                    ulonglong2 x23 = xr[1];
                    fma2(aq2[s], x01.x, wq[0]); fma2(ak2[s], x01.x, wk[0]); fma2(av2[s], x01.x, wv[0]);
                    fma2(aq2[s], x01.y, wq[1]); fma2(ak2[s], x01.y, wk[1]); fma2(av2[s], x01.y, wv[1]);
                    fma2(aq2[s], x23.x, wq[2]); fma2(ak2[s], x23.x, wk[2]); fma2(av2[s], x23.x, wv[2]);
                    fma2(aq2[s], x23.y, wq[3]); fma2(ak2[s], x23.y, wk[3]); fma2(av2[s], x23.y, wv[3]);
                }
            }
            __syncthreads();  // WS reads done before restage / qkv-buffer writes
        }

        // unpack -> qs/ks/vs
#pragma unroll
        for (int s = 0; s < 9; ++s) {
            int tok = tt * 17 + 2 * s;
            float lo, hi;
            up2(aq2[s], lo, hi);
            sm[QS_OFF + tok * QSTR + o32] = lo;
            if (s < 8) sm[QS_OFF + (tok + 1) * QSTR + o32] = hi;
            up2(ak2[s], lo, hi);
            sm[KS_OFF + tok * QSTR + o32] = lo;
            if (s < 8) sm[KS_OFF + (tok + 1) * QSTR + o32] = hi;
            up2(av2[s], lo, hi);
            sm[VS_OFF + tok * QSTR + o32] = lo;
            if (s < 8) sm[VS_OFF + (tok + 1) * QSTR + o32] = hi;
        }
        __syncthreads();

        // Attention: 544 rows = (tok, head-in-group)
        for (int r = tid; r < 544; r += 256) {
            int hl  = r / 136;
            int tok = r - hl * 136;
            int tl  = tok / 17;
            int n   = tok - tl * 17;
            const float* qp = sm + QS_OFF + tok * QSTR + hl * 8;
            const float* kb = sm + KS_OFF + tl * 17 * QSTR + hl * 8;
            const float* vb = sm + VS_OFF + tl * 17 * QSTR + hl * 8;
            const float* mb = sm + MB_OFF + hl * 289 + n * 17;
            float4 q0 = *reinterpret_cast<const float4*>(qp);
            float4 q1 = *reinterpret_cast<const float4*>(qp + 4);
            float ev[17];
            float mx = -3.4e38f;
#pragma unroll
            for (int m = 0; m < 17; ++m) {
                const float* kp = kb + m * QSTR;
                float4 k0 = *reinterpret_cast<const float4*>(kp);
                float4 k1 = *reinterpret_cast<const float4*>(kp + 4);
                float d0 = q0.x * k0.x;
                d0 = fmaf(q0.y, k0.y, d0); d0 = fmaf(q0.z, k0.z, d0); d0 = fmaf(q0.w, k0.w, d0);
                d0 = fmaf(q1.x, k1.x, d0); d0 = fmaf(q1.y, k1.y, d0);
                d0 = fmaf(q1.z, k1.z, d0); d0 = fmaf(q1.w, k1.w, d0);
                ev[m] = fmaf(d0, inv_s, mb[m]);
                mx = fmaxf(mx, ev[m]);
            }
            float s = 0.f;
#pragma unroll
            for (int m = 0; m < 17; ++m) { ev[m] = __expf(ev[m] - mx); s += ev[m]; }
            float inv = __fdividef(1.0f, s);
            float4 a0 = make_float4(0.f, 0.f, 0.f, 0.f);
            float4 a1 = make_float4(0.f, 0.f, 0.f, 0.f);
#pragma unroll
            for (int m = 0; m < 17; ++m) {
                const float* vp = vb + m * QSTR;
                float4 v0 = *reinterpret_cast<const float4*>(vp);
                float4 v1 = *reinterpret_cast<const float4*>(vp + 4);
                float pm = ev[m];
                a0.x = fmaf(pm, v0.x, a0.x); a0.y = fmaf(pm, v0.y, a0.y);
                a0.z = fmaf(pm, v0.z, a0.z); a0.w = fmaf(pm, v0.w, a0.w);
                a1.x = fmaf(pm, v1.x, a1.x); a1.y = fmaf(pm, v1.y, a1.y);
                a1.z = fmaf(pm, v1.z, a1.z); a1.w = fmaf(pm, v1.w, a1.w);
            }
            float acc[8] = {a0.x * inv, a0.y * inv, a0.z * inv, a0.w * inv,
                            a1.x * inv, a1.y * inv, a1.z * inv, a1.w * inv};
            int tta = tl;
            int loc = tok - tta * 17;
            int sl  = loc >> 1, par = loc & 1;
            float* ao = sm + AP_OFF + (tta * 9 + sl) * PSTR + par + 2 * (g * 32 + hl * 8);
#pragma unroll
            for (int e = 0; e < 8; ++e) ao[2 * e] = acc[e];
            if (loc == 16) {
#pragma unroll
                for (int e = 0; e < 8; ++e) ao[2 * e + 1] = acc[e];
            }
        }
        __syncthreads();
    }

    // ---- Phase C: packed conv1x1 + BN + ReLU; 4 chunks of 64 outputs ----
    for (int p = 0; p < 4; ++p) {
        const int ob = p * 64;
        u64 ac0[9], ac1[9];
#pragma unroll
        for (int s = 0; s < 9; ++s) { ac0[s] = 0ull; ac1[s] = 0ull; }

        for (int qi = 0; qi < 4; ++qi) {            // channel quarters (0-1: x, 2-3: attn-out)
            // stage [64 c][64 o] duplicated float2 = 8192 floats
            {
                float2* dst = reinterpret_cast<float2*>(sm + WS_OFF);
#pragma unroll
                for (int j = 0; j < 16; ++j) {
                    int idx = tid + j * 256;
                    int c = idx >> 6, o = idx & 63;
                    float w = __ldg(g_WcT + (size_t)(qi * 64 + c) * 256 + ob + o);
                    dst[idx] = make_float2(w, w);
                }
            }
            __syncthreads();
            const float* xbase = sm + ((qi < 2) ? XP_OFF : AP_OFF) + tt * 9 * PSTR + (qi & 1) * 128;
            for (int c4 = 0; c4 < 16; ++c4) {
                u64 wa[4], wb[4];
#pragma unroll
                for (int k = 0; k < 4; ++k) {
                    const u64* wrow = reinterpret_cast<const u64*>(sm + WS_OFF) + (c4 * 4 + k) * 64;
                    wa[k] = wrow[o32];
                    wb[k] = wrow[o32 + 32];
                }
#pragma unroll
                for (int s = 0; s < 9; ++s) {
                    const ulonglong2* xr = reinterpret_cast<const ulonglong2*>(xbase + s * PSTR + c4 * 8);
                    ulonglong2 x01 = xr[0];
                    ulonglong2 x23 = xr[1];
                    fma2(ac0[s], x01.x, wa[0]); fma2(ac1[s], x01.x, wb[0]);
                    fma2(ac0[s], x01.y, wa[1]); fma2(ac1[s], x01.y, wb[1]);
                    fma2(ac0[s], x23.x, wa[2]); fma2(ac1[s], x23.x, wb[2]);
                    fma2(ac0[s], x23.y, wa[3]); fma2(ac1[s], x23.y, wb[3]);
                }
            }
            __syncthreads();  // WS reads done before restage
        }

        // BN + ReLU -> Ys[64][137]
        {
            int oa = ob + o32, oc = oa + 32;
            float s0 = sm[BNS_OFF + oa], h0 = sm[BNB_OFF + oa];
            float s1 = sm[BNS_OFF + oc], h1 = sm[BNB_OFF + oc];
#pragma unroll
            for (int s = 0; s < 9; ++s) {
                int tok = tt * 17 + 2 * s;
                float lo, hi;
                up2(ac0[s], lo, hi);
                sm[YS_OFF + o32 * 137 + tok] = fmaxf(fmaf(lo, s0, h0), 0.0f);
                if (s < 8) sm[YS_OFF + o32 * 137 + tok + 1] = fmaxf(fmaf(hi, s0, h0), 0.0f);
                up2(ac1[s], lo, hi);
                sm[YS_OFF + (o32 + 32) * 137 + tok] = fmaxf(fmaf(lo, s1, h1), 0.0f);
                if (s < 8) sm[YS_OFF + (o32 + 32) * 137 + tok + 1] = fmaxf(fmaf(hi, s1, h1), 0.0f);
            }
        }
        __syncthreads();
        // coalesced store: out[(b*256+o)*8704 + t0*17 + tok]
        {
            float* ob_ptr = out + (size_t)(b * 256 + ob) * 8704 + (size_t)t0 * 17;
            for (int idx = tid; idx < 64 * 136; idx += 256) {
                int ol = idx / 136;
                int tok = idx - ol * 136;
                ob_ptr[(size_t)ol * 8704 + tok] = sm[YS_OFF + ol * 137 + tok];
            }
        }
        __syncthreads();
    }
}

// ---------------- launch ----------------
extern "C" void kernel_launch(void* const* d_in, const int* in_sizes, int n_in,
                              void* d_out, int out_size) {
    const float* x      = (const float*)d_in[0];
    const float* adj    = (const float*)d_in[1];
    const float* Wq     = (const float*)d_in[2];
    const float* Wk     = (const float*)d_in[3];
    const float* Wv     = (const float*)d_in[4];
    const float* adj2   = (const float*)d_in[5];
    const float* convw  = (const float*)d_in[6];
    const float* bng    = (const float*)d_in[7];
    const float* bnb    = (const float*)d_in[8];
    const float* bnm    = (const float*)d_in[9];
    const float* bnv    = (const float*)d_in[10];
    float* out = (float*)d_out;

    cudaFuncSetAttribute(gab_kernel, cudaFuncAttributeMaxDynamicSharedMemorySize, SMEM_BYTES);

    prep_kernel<<<(4 * 128 * 96 + 256 * 256 + 255) / 256, 256>>>(Wq, Wk, Wv, convw);
    gab_kernel<<<2048, 256, SMEM_BYTES>>>(x, adj, adj2, bng, bnb, bnm, bnv, out);
}

// round 11
// speedup vs baseline: 1.3927x; 1.3927x over previous
#include <cuda_runtime.h>
#include <cuda_bf16.h>
#include <cstdint>
#include <cstddef>

typedef unsigned int u32;

#define NEG_INFF (-9.0e15f)
#define BN_EPS 1e-5f

// ---------------- smem layout (bytes) ----------------
// A tiles: [136 tok][264 k] bf16, stride 528 B (ldmatrix conflict-free: 33%8==1)
#define AH_B   0u
#define AL_B   71808u          // 136*528
#define QS_B   143616u         // qs[136][36] f32 = 19584
#define KS_B   163200u
#define VS_B   182784u
#define MB_B   202368u         // mask 4*289 f32 = 4624
#define BS_B   206992u         // weight stage: qkv 17408 B, conv 16896 B
#define BNS_B  224400u         // bn scale 256 f32
#define BNB_B  225424u
#define SMEM_BYTES 226448u

// ---------------- pre-packed bf16 weight images ----------------
// g_Bqkv[g][third][hi/lo][n*136+c]: third 0=q,1=k,2=v (32 cols each), k-stride 136
__device__ __align__(16) __nv_bfloat16 g_Bqkv[4][3][2][32 * 136];
// g_Bconv[cb][hi/lo][n*264+c]: 16 chunks of 16 outputs, k-stride 264 (K=256)
__device__ __align__(16) __nv_bfloat16 g_Bconv[16][2][16 * 264];

__global__ void prep_kernel(const float* __restrict__ Wq, const float* __restrict__ Wk,
                            const float* __restrict__ Wv, const float* __restrict__ cw) {
    int i = blockIdx.x * blockDim.x + threadIdx.x;
    if (i < 4 * 96 * 128) {
        int g = i / 12288; int r = i - g * 12288;
        int n = r >> 7, c = r & 127;              // n: group col 0..95, c: channel
        int third = n >> 5, nl = n & 31;
        int o = nl;                               // col within part
        int h = g * 4 + (o >> 3), e = o & 7;
        const float* W = (third == 0) ? Wq : (third == 1 ? Wk : Wv);
        float w = W[h * 1024 + c * 8 + e];        // W[h][c][e] (16,128,8)
        __nv_bfloat16 hi = __float2bfloat16_rn(w);
        __nv_bfloat16 lo = __float2bfloat16_rn(w - __bfloat162float(hi));
        g_Bqkv[g][third][0][nl * 136 + c] = hi;
        g_Bqkv[g][third][1][nl * 136 + c] = lo;
    } else {
        int j = i - 4 * 96 * 128;
        if (j < 16 * 16 * 256) {
            int cb = j / 4096; int r = j - cb * 4096;
            int n = r >> 8, c = r & 255;
            int o = cb * 16 + n;
            float w = cw[o * 256 + c];
            __nv_bfloat16 hi = __float2bfloat16_rn(w);
            __nv_bfloat16 lo = __float2bfloat16_rn(w - __bfloat162float(hi));
            g_Bconv[cb][0][n * 264 + c] = hi;
            g_Bconv[cb][1][n * 264 + c] = lo;
        }
    }
}

// ---------------- warp mma helpers ----------------
__device__ __forceinline__ u32 smem_u32(const void* p) {
    u32 a;
    asm("{ .reg .u64 t; cvta.to.shared.u64 t, %1; cvt.u32.u64 %0, t; }" : "=r"(a) : "l"(p));
    return a;
}
__device__ __forceinline__ void ldsm4(u32* r, u32 a) {
    asm volatile("ldmatrix.sync.aligned.m8n8.x4.shared.b16 {%0,%1,%2,%3}, [%4];"
                 : "=r"(r[0]), "=r"(r[1]), "=r"(r[2]), "=r"(r[3]) : "r"(a));
}
__device__ __forceinline__ void ldsm2(u32* r, u32 a) {
    asm volatile("ldmatrix.sync.aligned.m8n8.x2.shared.b16 {%0,%1}, [%2];"
                 : "=r"(r[0]), "=r"(r[1]) : "r"(a));
}
__device__ __forceinline__ void mma16816(float* c, const u32* a, const u32* b) {
    asm volatile(
        "mma.sync.aligned.m16n8k16.row.col.f32.bf16.bf16.f32 "
        "{%0,%1,%2,%3}, {%4,%5,%6,%7}, {%8,%9}, {%0,%1,%2,%3};"
        : "+f"(c[0]), "+f"(c[1]), "+f"(c[2]), "+f"(c[3])
        : "r"(a[0]), "r"(a[1]), "r"(a[2]), "r"(a[3]), "r"(b[0]), "r"(b[1]));
}
__device__ __forceinline__ void split2(float a, float b, u32& hu, u32& lu) {
    __nv_bfloat16 ha = __float2bfloat16_rn(a), hb = __float2bfloat16_rn(b);
    float ra = a - __bfloat162float(ha), rb = b - __bfloat162float(hb);
    __nv_bfloat16 la = __float2bfloat16_rn(ra), lb = __float2bfloat16_rn(rb);
    hu = (u32)__bfloat16_as_ushort(ha) | ((u32)__bfloat16_as_ushort(hb) << 16);
    lu = (u32)__bfloat16_as_ushort(la) | ((u32)__bfloat16_as_ushort(lb) << 16);
}

extern __shared__ __align__(16) unsigned char sp[];

__global__ void __launch_bounds__(256, 1)
gab_kernel(const float* __restrict__ x, const float* __restrict__ adj,
           const float* __restrict__ adj2,
           const float* __restrict__ bng, const float* __restrict__ bnbv,
           const float* __restrict__ bnm, const float* __restrict__ bnv,
           float* __restrict__ out) {
    const u32 sb = smem_u32(sp);
    const int b  = blockIdx.x >> 6;
    const int tb = blockIdx.x & 63;
    const int t0 = tb * 8;
    const int tid  = threadIdx.x;
    const int lane = tid & 31;
    const int wid  = tid >> 5;

    // ---- Phase A: load X, bf16-split into A_hi/A_lo [tok][c] (c: 0..127) ----
    {
        const float* xb = x + (size_t)b * 128 * 8704 + (size_t)t0 * 17;
        for (int d4 = wid; d4 < 32; d4 += 8) {
            const float* s0 = xb + (size_t)(d4 * 4 + 0) * 8704;
            const float* s1 = xb + (size_t)(d4 * 4 + 1) * 8704;
            const float* s2 = xb + (size_t)(d4 * 4 + 2) * 8704;
            const float* s3 = xb + (size_t)(d4 * 4 + 3) * 8704;
            for (int tok = lane; tok < 136; tok += 32) {
                float v0 = s0[tok], v1 = s1[tok], v2 = s2[tok], v3 = s3[tok];
                u32 h01, l01, h23, l23;
                split2(v0, v1, h01, l01);
                split2(v2, v3, h23, l23);
                u32 off = (u32)tok * 528u + (u32)d4 * 8u;
                *(uint2*)(sp + AH_B + off) = make_uint2(h01, h23);
                *(uint2*)(sp + AL_B + off) = make_uint2(l01, l23);
            }
        }
    }
    // ---- BN fold ----
    {
        float sc = bng[tid] * rsqrtf(bnv[tid] + BN_EPS);
        ((float*)(sp + BNS_B))[tid] = sc;
        ((float*)(sp + BNB_B))[tid] = bnbv[tid] - bnm[tid] * sc;
    }

    const float inv_s = 0.3535533905932738f;   // 1/sqrt(8)
    float* qsf = (float*)(sp + QS_B);
    float* ksf = (float*)(sp + KS_B);
    float* vsf = (float*)(sp + VS_B);
    float* mbf = (float*)(sp + MB_B);
    const int row_lo0 = (lane >> 2);
    const int col0 = (lane & 3) * 2;

    // ---- Phase B: 4 head-groups; per group: 3 thirds (q/k/v) of MMA, then attention ----
    for (int g = 0; g < 4; ++g) {
        for (int third = 0; third < 3; ++third) {
            // stage hi+lo weights for this third (17408 B = 1088 uint4)
            {
                const uint4* src = (const uint4*)&g_Bqkv[g][third][0][0];
                uint4* dst = (uint4*)(sp + BS_B);
                for (int j = tid; j < 1088; j += 256) dst[j] = __ldg(src + j);
            }
            if (third == 0) {
                for (int idx = tid; idx < 4 * 289; idx += 256) {
                    int hl = idx / 289, r = idx - hl * 289;
                    int n = r / 17, m = r - n * 17;
                    int hh = g * 4 + hl;
                    float a = 0.5f * (adj[n * 17 + m] + adj[m * 17 + n])
                            + 0.5f * (adj2[hh * 289 + n * 17 + m] + adj2[hh * 289 + m * 17 + n]);
                    mbf[idx] = (a > 0.0f) ? 0.0f : NEG_INFF;
                }
            }
            __syncthreads();

            for (int mt = wid; mt < 9; mt += 8) {
                u32 abase = sb + AH_B + (u32)(mt * 16 + (lane & 15)) * 528u + (u32)((lane >> 4) * 16);
                u32 albase = abase + (AL_B - AH_B);
                u32 bbase = sb + BS_B + (u32)(lane & 7) * 272u + (u32)(((lane >> 3) & 1) * 16);
                u32 ah[8][4];
#pragma unroll
                for (int k = 0; k < 8; ++k) ldsm4(ah[k], abase + (u32)k * 32u);
                float c[4][4];
#pragma unroll
                for (int nt = 0; nt < 4; ++nt)
#pragma unroll
                    for (int e = 0; e < 4; ++e) c[nt][e] = 0.f;
#pragma unroll
                for (int k = 0; k < 8; ++k) {
                    u32 al[4];
                    ldsm4(al, albase + (u32)k * 32u);
#pragma unroll
                    for (int nt = 0; nt < 4; ++nt) {
                        u32 bh[2], bl[2];
                        ldsm2(bh, bbase + (u32)(nt * 8) * 272u + (u32)k * 32u);
                        ldsm2(bl, bbase + 8704u + (u32)(nt * 8) * 272u + (u32)k * 32u);
                        mma16816(c[nt], ah[k], bh);
                        mma16816(c[nt], al, bh);
                        mma16816(c[nt], ah[k], bl);
                    }
                }
                // epilogue: write to q/k/v buffers (f32, stride 36)
                float* buf = (third == 0) ? qsf : (third == 1 ? ksf : vsf);
                int rlo = mt * 16 + row_lo0, rhi = rlo + 8;
#pragma unroll
                for (int nt = 0; nt < 4; ++nt) {
                    int oc = nt * 8 + col0;
                    *(float2*)(buf + rlo * 36 + oc) = make_float2(c[nt][0], c[nt][1]);
                    if (rhi < 136)
                        *(float2*)(buf + rhi * 36 + oc) = make_float2(c[nt][2], c[nt][3]);
                }
            }
            __syncthreads();
        }

        // ---- attention (fp32 scalar, 544 rows) ----
        for (int r = tid; r < 544; r += 256) {
            int hl  = r / 136;
            int tok = r - hl * 136;
            int tl  = tok / 17;
            int n   = tok - tl * 17;
            const float* qp = qsf + tok * 36 + hl * 8;
            const float* kb = ksf + (tl * 17) * 36 + hl * 8;
            const float* vb = vsf + (tl * 17) * 36 + hl * 8;
            const float* mb = mbf + hl * 289 + n * 17;
            float4 q0 = *(const float4*)(qp);
            float4 q1 = *(const float4*)(qp + 4);
            float ev[17];
            float mx = -3.4e38f;
#pragma unroll
            for (int m = 0; m < 17; ++m) {
                const float* kp = kb + m * 36;
                float4 k0 = *(const float4*)(kp);
                float4 k1 = *(const float4*)(kp + 4);
                float d0 = q0.x * k0.x;
                d0 = fmaf(q0.y, k0.y, d0); d0 = fmaf(q0.z, k0.z, d0); d0 = fmaf(q0.w, k0.w, d0);
                d0 = fmaf(q1.x, k1.x, d0); d0 = fmaf(q1.y, k1.y, d0);
                d0 = fmaf(q1.z, k1.z, d0); d0 = fmaf(q1.w, k1.w, d0);
                ev[m] = fmaf(d0, inv_s, mb[m]);
                mx = fmaxf(mx, ev[m]);
            }
            float s = 0.f;
#pragma unroll
            for (int m = 0; m < 17; ++m) { ev[m] = __expf(ev[m] - mx); s += ev[m]; }
            float inv = __fdividef(1.0f, s);
            float a0x = 0.f, a0y = 0.f, a0z = 0.f, a0w = 0.f;
            float a1x = 0.f, a1y = 0.f, a1z = 0.f, a1w = 0.f;
#pragma unroll
            for (int m = 0; m < 17; ++m) {
                const float* vp = vb + m * 36;
                float4 v0 = *(const float4*)(vp);
                float4 v1 = *(const float4*)(vp + 4);
                float pm = ev[m];
                a0x = fmaf(pm, v0.x, a0x); a0y = fmaf(pm, v0.y, a0y);
                a0z = fmaf(pm, v0.z, a0z); a0w = fmaf(pm, v0.w, a0w);
                a1x = fmaf(pm, v1.x, a1x); a1y = fmaf(pm, v1.y, a1y);
                a1z = fmaf(pm, v1.z, a1z); a1w = fmaf(pm, v1.w, a1w);
            }
            // split to bf16 hi/lo and store into A cols 128 + g*32 + hl*8
            u32 h0, l0, h1, l1, h2, l2, h3, l3;
            split2(a0x * inv, a0y * inv, h0, l0);
            split2(a0z * inv, a0w * inv, h1, l1);
            split2(a1x * inv, a1y * inv, h2, l2);
            split2(a1z * inv, a1w * inv, h3, l3);
            u32 off = (u32)tok * 528u + 256u + (u32)g * 64u + (u32)hl * 16u;
            *(uint4*)(sp + AH_B + off) = make_uint4(h0, h1, h2, h3);
            *(uint4*)(sp + AL_B + off) = make_uint4(l0, l1, l2, l3);
        }
        __syncthreads();
    }

    // ---- Phase C: conv1x1 via MMA (K=256), 16 chunks of 16 outputs ----
    const float* bnsc = (const float*)(sp + BNS_B);
    const float* bnsh = (const float*)(sp + BNB_B);
    float* ysf = (float*)(sp + QS_B);   // Ys[136][18]
    for (int cb = 0; cb < 16; ++cb) {
        {
            const uint4* src = (const uint4*)&g_Bconv[cb][0][0];
            uint4* dst = (uint4*)(sp + BS_B);
            for (int j = tid; j < 1056; j += 256) dst[j] = __ldg(src + j);
        }
        __syncthreads();

        for (int mt = wid; mt < 9; mt += 8) {
            u32 abase = sb + AH_B + (u32)(mt * 16 + (lane & 15)) * 528u + (u32)((lane >> 4) * 16);
            u32 albase = abase + (AL_B - AH_B);
            u32 bbase = sb + BS_B + (u32)(lane & 7) * 528u + (u32)(((lane >> 3) & 1) * 16);
            float c[2][4];
#pragma unroll
            for (int nt = 0; nt < 2; ++nt)
#pragma unroll
                for (int e = 0; e < 4; ++e) c[nt][e] = 0.f;
#pragma unroll 4
            for (int k = 0; k < 16; ++k) {
                u32 ah[4], al[4];
                ldsm4(ah, abase + (u32)k * 32u);
                ldsm4(al, albase + (u32)k * 32u);
#pragma unroll
                for (int nt = 0; nt < 2; ++nt) {
                    u32 bh[2], bl[2];
                    ldsm2(bh, bbase + (u32)(nt * 8) * 528u + (u32)k * 32u);
                    ldsm2(bl, bbase + 8448u + (u32)(nt * 8) * 528u + (u32)k * 32u);
                    mma16816(c[nt], ah, bh);
                    mma16816(c[nt], al, bh);
                    mma16816(c[nt], ah, bl);
                }
            }
            // BN + ReLU -> Ys[136][18]
            int rlo = mt * 16 + row_lo0, rhi = rlo + 8;
#pragma unroll
            for (int nt = 0; nt < 2; ++nt) {
                int og = cb * 16 + nt * 8 + col0;
                float s0 = bnsc[og], h0 = bnsh[og];
                float s1 = bnsc[og + 1], h1 = bnsh[og + 1];
                float y0 = fmaxf(fmaf(c[nt][0], s0, h0), 0.0f);
                float y1 = fmaxf(fmaf(c[nt][1], s1, h1), 0.0f);
                *(float2*)(ysf + rlo * 18 + nt * 8 + col0) = make_float2(y0, y1);
                if (rhi < 136) {
                    float y2 = fmaxf(fmaf(c[nt][2], s0, h0), 0.0f);
                    float y3 = fmaxf(fmaf(c[nt][3], s1, h1), 0.0f);
                    *(float2*)(ysf + rhi * 18 + nt * 8 + col0) = make_float2(y2, y3);
                }
            }
        }
        __syncthreads();
        // coalesced store: out[(b*256 + cb*16 + ol)*8704 + t0*17 + tok]
        {
            float* op = out + (size_t)(b * 256 + cb * 16) * 8704 + (size_t)t0 * 17;
            for (int idx = tid; idx < 16 * 136; idx += 256) {
                int ol = idx / 136;
                int tok = idx - ol * 136;
                op[(size_t)ol * 8704 + tok] = ysf[tok * 18 + ol];
            }
        }
        __syncthreads();
    }
}

// ---------------- launch ----------------
extern "C" void kernel_launch(void* const* d_in, const int* in_sizes, int n_in,
                              void* d_out, int out_size) {
    const float* x      = (const float*)d_in[0];
    const float* adj    = (const float*)d_in[1];
    const float* Wq     = (const float*)d_in[2];
    const float* Wk     = (const float*)d_in[3];
    const float* Wv     = (const float*)d_in[4];
    const float* adj2   = (const float*)d_in[5];
    const float* convw  = (const float*)d_in[6];
    const float* bng    = (const float*)d_in[7];
    const float* bnb    = (const float*)d_in[8];
    const float* bnm    = (const float*)d_in[9];
    const float* bnv    = (const float*)d_in[10];
    float* out = (float*)d_out;

    cudaFuncSetAttribute(gab_kernel, cudaFuncAttributeMaxDynamicSharedMemorySize, SMEM_BYTES);

    prep_kernel<<<(4 * 96 * 128 + 16 * 16 * 256 + 255) / 256, 256>>>(Wq, Wk, Wv, convw);
    gab_kernel<<<2048, 256, SMEM_BYTES>>>(x, adj, adj2, bng, bnb, bnm, bnv, out);
}

// round 12
// speedup vs baseline: 1.6591x; 1.1913x over previous
#include <cuda_runtime.h>
#include <cuda_bf16.h>
#include <cstdint>
#include <cstddef>

typedef unsigned int u32;

#define NEG_INFF (-9.0e15f)
#define BN_EPS 1e-5f

// ---------------- smem layout (bytes) ----------------
// A tiles: [136 tok][264 k] bf16, stride 528 B (ldmatrix conflict-free: 33%8==1)
#define AH_B   0u
#define AL_B   71808u          // 136*528
#define QS_B   143616u         // qs[136][36] f32 = 19584
#define KS_B   163200u
#define VS_B   182784u
#define MB_B   202368u         // mask 4*289 f32 = 4624
#define BS_B   206992u         // weight stage: qkv 17408 B, conv 16896 B
#define BNS_B  224400u         // bn scale 256 f32
#define BNB_B  225424u
#define SMEM_BYTES 226448u

// ---------------- pre-packed bf16 weight images ----------------
// g_Bqkv[g][third][hi/lo][n*136+c]: third 0=q,1=k,2=v (32 cols each), k-stride 136
__device__ __align__(16) __nv_bfloat16 g_Bqkv[4][3][2][32 * 136];
// g_Bconv[cb][hi/lo][n*264+c]: 16 chunks of 16 outputs, k-stride 264 (K=256)
__device__ __align__(16) __nv_bfloat16 g_Bconv[16][2][16 * 264];

__global__ void prep_kernel(const float* __restrict__ Wq, const float* __restrict__ Wk,
                            const float* __restrict__ Wv, const float* __restrict__ cw) {
    int i = blockIdx.x * blockDim.x + threadIdx.x;
    if (i < 4 * 96 * 128) {
        int g = i / 12288; int r = i - g * 12288;
        int n = r >> 7, c = r & 127;
        int third = n >> 5, nl = n & 31;
        int h = g * 4 + (nl >> 3), e = nl & 7;
        const float* W = (third == 0) ? Wq : (third == 1 ? Wk : Wv);
        float w = W[h * 1024 + c * 8 + e];        // W[h][c][e] (16,128,8)
        __nv_bfloat16 hi = __float2bfloat16_rn(w);
        __nv_bfloat16 lo = __float2bfloat16_rn(w - __bfloat162float(hi));
        g_Bqkv[g][third][0][nl * 136 + c] = hi;
        g_Bqkv[g][third][1][nl * 136 + c] = lo;
    } else {
        int j = i - 4 * 96 * 128;
        if (j < 16 * 16 * 256) {
            int cb = j / 4096; int r = j - cb * 4096;
            int n = r >> 8, c = r & 255;
            int o = cb * 16 + n;
            float w = cw[o * 256 + c];
            __nv_bfloat16 hi = __float2bfloat16_rn(w);
            __nv_bfloat16 lo = __float2bfloat16_rn(w - __bfloat162float(hi));
            g_Bconv[cb][0][n * 264 + c] = hi;
            g_Bconv[cb][1][n * 264 + c] = lo;
        }
    }
}

// ---------------- warp mma helpers ----------------
__device__ __forceinline__ u32 smem_u32(const void* p) {
    u32 a;
    asm("{ .reg .u64 t; cvta.to.shared.u64 t, %1; cvt.u32.u64 %0, t; }" : "=r"(a) : "l"(p));
    return a;
}
__device__ __forceinline__ void ldsm4(u32* r, u32 a) {
    asm volatile("ldmatrix.sync.aligned.m8n8.x4.shared.b16 {%0,%1,%2,%3}, [%4];"
                 : "=r"(r[0]), "=r"(r[1]), "=r"(r[2]), "=r"(r[3]) : "r"(a));
}
__device__ __forceinline__ void ldsm2(u32* r, u32 a) {
    asm volatile("ldmatrix.sync.aligned.m8n8.x2.shared.b16 {%0,%1}, [%2];"
                 : "=r"(r[0]), "=r"(r[1]) : "r"(a));
}
__device__ __forceinline__ void mma16816(float* c, const u32* a, const u32* b) {
    asm volatile(
        "mma.sync.aligned.m16n8k16.row.col.f32.bf16.bf16.f32 "
        "{%0,%1,%2,%3}, {%4,%5,%6,%7}, {%8,%9}, {%0,%1,%2,%3};"
        : "+f"(c[0]), "+f"(c[1]), "+f"(c[2]), "+f"(c[3])
        : "r"(a[0]), "r"(a[1]), "r"(a[2]), "r"(a[3]), "r"(b[0]), "r"(b[1]));
}
__device__ __forceinline__ void split2(float a, float b, u32& hu, u32& lu) {
    __nv_bfloat16 ha = __float2bfloat16_rn(a), hb = __float2bfloat16_rn(b);
    float ra = a - __bfloat162float(ha), rb = b - __bfloat162float(hb);
    __nv_bfloat16 la = __float2bfloat16_rn(ra), lb = __float2bfloat16_rn(rb);
    hu = (u32)__bfloat16_as_ushort(ha) | ((u32)__bfloat16_as_ushort(hb) << 16);
    lu = (u32)__bfloat16_as_ushort(la) | ((u32)__bfloat16_as_ushort(lb) << 16);
}

extern __shared__ __align__(16) unsigned char sp[];

__global__ void __launch_bounds__(512, 1)
gab_kernel(const float* __restrict__ x, const float* __restrict__ adj,
           const float* __restrict__ adj2,
           const float* __restrict__ bng, const float* __restrict__ bnbv,
           const float* __restrict__ bnm, const float* __restrict__ bnv,
           float* __restrict__ out) {
    const u32 sb = smem_u32(sp);
    const int b  = blockIdx.x >> 6;
    const int tb = blockIdx.x & 63;
    const int t0 = tb * 8;
    const int tid  = threadIdx.x;
    const int lane = tid & 31;
    const int wid  = tid >> 5;

    // ---- register prefetch of first weight stage (overlaps Phase A) ----
    uint4 pf0, pf1, pf2;
    int pcnt = 1088;                      // uint4 count currently in regs
    {
        const uint4* src = (const uint4*)&g_Bqkv[0][0][0][0];
        pf0 = __ldg(src + tid);
        if (tid + 512 < 1088)  pf1 = __ldg(src + tid + 512);
        if (tid + 1024 < 1088) pf2 = __ldg(src + tid + 1024);
    }

    // ---- Phase A: load X, bf16-split into A_hi/A_lo [tok][c] (c: 0..127) ----
    {
        const float* xb = x + (size_t)b * 128 * 8704 + (size_t)t0 * 17;
        for (int d4 = wid; d4 < 32; d4 += 16) {
            const float* s0 = xb + (size_t)(d4 * 4 + 0) * 8704;
            const float* s1 = xb + (size_t)(d4 * 4 + 1) * 8704;
            const float* s2 = xb + (size_t)(d4 * 4 + 2) * 8704;
            const float* s3 = xb + (size_t)(d4 * 4 + 3) * 8704;
            for (int tok = lane; tok < 136; tok += 32) {
                float v0 = s0[tok], v1 = s1[tok], v2 = s2[tok], v3 = s3[tok];
                u32 h01, l01, h23, l23;
                split2(v0, v1, h01, l01);
                split2(v2, v3, h23, l23);
                u32 off = (u32)tok * 528u + (u32)d4 * 8u;
                *(uint2*)(sp + AH_B + off) = make_uint2(h01, h23);
                *(uint2*)(sp + AL_B + off) = make_uint2(l01, l23);
            }
        }
    }
    // ---- BN fold ----
    if (tid < 256) {
        float sc = bng[tid] * rsqrtf(bnv[tid] + BN_EPS);
        ((float*)(sp + BNS_B))[tid] = sc;
        ((float*)(sp + BNB_B))[tid] = bnbv[tid] - bnm[tid] * sc;
    }

    const float inv_s = 0.3535533905932738f;   // 1/sqrt(8)
    float* qsf = (float*)(sp + QS_B);
    float* ksf = (float*)(sp + KS_B);
    float* vsf = (float*)(sp + VS_B);
    float* mbf = (float*)(sp + MB_B);
    const int row_lo0 = (lane >> 2);
    const int col0 = (lane & 3) * 2;

    // ---- Phase B: 4 head-groups; per group: 3 thirds (q/k/v), then attention ----
    for (int g = 0; g < 4; ++g) {
        for (int third = 0; third < 3; ++third) {
            __syncthreads();   // prev BS reads done / Phase A visible
            // commit prefetched stage to BS
            {
                uint4* dst = (uint4*)(sp + BS_B);
                dst[tid] = pf0;
                if (tid + 512 < pcnt)  dst[tid + 512] = pf1;
                if (tid + 1024 < pcnt) dst[tid + 1024] = pf2;
            }
            // prefetch next stage
            {
                int st = g * 3 + third;
                const uint4* nsrc;
                int ncnt;
                if (st < 11) {
                    int ns = st + 1;
                    nsrc = (const uint4*)&g_Bqkv[ns / 3][ns % 3][0][0];
                    ncnt = 1088;
                } else {
                    nsrc = (const uint4*)&g_Bconv[0][0][0];
                    ncnt = 1056;
                }
                pf0 = __ldg(nsrc + tid);
                if (tid + 512 < ncnt)  pf1 = __ldg(nsrc + tid + 512);
                if (tid + 1024 < ncnt) pf2 = __ldg(nsrc + tid + 1024);
                pcnt = ncnt;
            }
            if (third == 0) {
                for (int idx = tid; idx < 4 * 289; idx += 512) {
                    int hl = idx / 289, r = idx - hl * 289;
                    int n = r / 17, m = r - n * 17;
                    int hh = g * 4 + hl;
                    float a = 0.5f * (adj[n * 17 + m] + adj[m * 17 + n])
                            + 0.5f * (adj2[hh * 289 + n * 17 + m] + adj2[hh * 289 + m * 17 + n]);
                    mbf[idx] = (a > 0.0f) ? 0.0f : NEG_INFF;
                }
            }
            __syncthreads();

            // 18 units = (mt 0..8, n-half 0..1)
            for (int u = wid; u < 18; u += 16) {
                int mt = u >> 1, nh = u & 1;
                u32 abase = sb + AH_B + (u32)(mt * 16 + (lane & 15)) * 528u + (u32)((lane >> 4) * 16);
                u32 albase = abase + (AL_B - AH_B);
                u32 bbase = sb + BS_B + (u32)(lane & 7) * 272u + (u32)(((lane >> 3) & 1) * 16);
                u32 ah[8][4];
#pragma unroll
                for (int k = 0; k < 8; ++k) ldsm4(ah[k], abase + (u32)k * 32u);
                float c[2][4];
#pragma unroll
                for (int nt = 0; nt < 2; ++nt)
#pragma unroll
                    for (int e = 0; e < 4; ++e) c[nt][e] = 0.f;
#pragma unroll
                for (int k = 0; k < 8; ++k) {
                    u32 al[4];
                    ldsm4(al, albase + (u32)k * 32u);
#pragma unroll
                    for (int nt = 0; nt < 2; ++nt) {
                        int ncol = nh * 2 + nt;
                        u32 bh[2], bl[2];
                        ldsm2(bh, bbase + (u32)(ncol * 8) * 272u + (u32)k * 32u);
                        ldsm2(bl, bbase + 8704u + (u32)(ncol * 8) * 272u + (u32)k * 32u);
                        mma16816(c[nt], ah[k], bh);
                        mma16816(c[nt], al, bh);
                        mma16816(c[nt], ah[k], bl);
                    }
                }
                float* buf = (third == 0) ? qsf : (third == 1 ? ksf : vsf);
                int rlo = mt * 16 + row_lo0, rhi = rlo + 8;
#pragma unroll
                for (int nt = 0; nt < 2; ++nt) {
                    int oc = (nh * 2 + nt) * 8 + col0;
                    *(float2*)(buf + rlo * 36 + oc) = make_float2(c[nt][0], c[nt][1]);
                    if (rhi < 136)
                        *(float2*)(buf + rhi * 36 + oc) = make_float2(c[nt][2], c[nt][3]);
                }
            }
        }
        __syncthreads();   // q/k/v epilogues visible

        // ---- attention (fp32 scalar, 544 rows) ----
        for (int r = tid; r < 544; r += 512) {
            int hl  = r / 136;
            int tok = r - hl * 136;
            int tl  = tok / 17;
            int n   = tok - tl * 17;
            const float* qp = qsf + tok * 36 + hl * 8;
            const float* kb = ksf + (tl * 17) * 36 + hl * 8;
            const float* vb = vsf + (tl * 17) * 36 + hl * 8;
            const float* mb = mbf + hl * 289 + n * 17;
            float4 q0 = *(const float4*)(qp);
            float4 q1 = *(const float4*)(qp + 4);
            float ev[17];
            float mx = -3.4e38f;
#pragma unroll
            for (int m = 0; m < 17; ++m) {
                const float* kp = kb + m * 36;
                float4 k0 = *(const float4*)(kp);
                float4 k1 = *(const float4*)(kp + 4);
                float d0 = q0.x * k0.x;
                d0 = fmaf(q0.y, k0.y, d0); d0 = fmaf(q0.z, k0.z, d0); d0 = fmaf(q0.w, k0.w, d0);
                d0 = fmaf(q1.x, k1.x, d0); d0 = fmaf(q1.y, k1.y, d0);
                d0 = fmaf(q1.z, k1.z, d0); d0 = fmaf(q1.w, k1.w, d0);
                ev[m] = fmaf(d0, inv_s, mb[m]);
                mx = fmaxf(mx, ev[m]);
            }
            float s = 0.f;
#pragma unroll
            for (int m = 0; m < 17; ++m) { ev[m] = __expf(ev[m] - mx); s += ev[m]; }
            float inv = __fdividef(1.0f, s);
            float a0x = 0.f, a0y = 0.f, a0z = 0.f, a0w = 0.f;
            float a1x = 0.f, a1y = 0.f, a1z = 0.f, a1w = 0.f;
#pragma unroll
            for (int m = 0; m < 17; ++m) {
                const float* vp = vb + m * 36;
                float4 v0 = *(const float4*)(vp);
                float4 v1 = *(const float4*)(vp + 4);
                float pm = ev[m];
                a0x = fmaf(pm, v0.x, a0x); a0y = fmaf(pm, v0.y, a0y);
                a0z = fmaf(pm, v0.z, a0z); a0w = fmaf(pm, v0.w, a0w);
                a1x = fmaf(pm, v1.x, a1x); a1y = fmaf(pm, v1.y, a1y);
                a1z = fmaf(pm, v1.z, a1z); a1w = fmaf(pm, v1.w, a1w);
            }
            u32 h0, l0, h1, l1, h2, l2, h3, l3;
            split2(a0x * inv, a0y * inv, h0, l0);
            split2(a0z * inv, a0w * inv, h1, l1);
            split2(a1x * inv, a1y * inv, h2, l2);
            split2(a1z * inv, a1w * inv, h3, l3);
            u32 off = (u32)tok * 528u + 256u + (u32)g * 64u + (u32)hl * 16u;
            *(uint4*)(sp + AH_B + off) = make_uint4(h0, h1, h2, h3);
            *(uint4*)(sp + AL_B + off) = make_uint4(l0, l1, l2, l3);
        }
    }

    // ---- Phase C: conv1x1 via MMA (K=256), 16 chunks of 16 outputs ----
    const float* bnsc = (const float*)(sp + BNS_B);
    const float* bnsh = (const float*)(sp + BNB_B);
    float* ysf = (float*)(sp + QS_B);   // Ys[136][18]
    for (int cb = 0; cb < 16; ++cb) {
        __syncthreads();   // prev store reads done; attention writes visible (cb=0)
        {
            uint4* dst = (uint4*)(sp + BS_B);
            dst[tid] = pf0;
            if (tid + 512 < pcnt)  dst[tid + 512] = pf1;
            if (tid + 1024 < pcnt) dst[tid + 1024] = pf2;
        }
        if (cb < 15) {
            const uint4* nsrc = (const uint4*)&g_Bconv[cb + 1][0][0];
            pf0 = __ldg(nsrc + tid);
            if (tid + 512 < 1056) pf1 = __ldg(nsrc + tid + 512);
            if (tid + 1024 < 1056) pf2 = __ldg(nsrc + tid + 1024);
            pcnt = 1056;
        }
        __syncthreads();

        // 18 units = (mt 0..8, nt 0..1)
        for (int u = wid; u < 18; u += 16) {
            int mt = u >> 1, nt = u & 1;
            u32 abase = sb + AH_B + (u32)(mt * 16 + (lane & 15)) * 528u + (u32)((lane >> 4) * 16);
            u32 albase = abase + (AL_B - AH_B);
            u32 bbase = sb + BS_B + (u32)(lane & 7) * 528u + (u32)(((lane >> 3) & 1) * 16)
                      + (u32)(nt * 8) * 528u;
            float c[4];
#pragma unroll
            for (int e = 0; e < 4; ++e) c[e] = 0.f;
#pragma unroll 4
            for (int k = 0; k < 16; ++k) {
                u32 ah[4], al[4];
                ldsm4(ah, abase + (u32)k * 32u);
                ldsm4(al, albase + (u32)k * 32u);
                u32 bh[2], bl[2];
                ldsm2(bh, bbase + (u32)k * 32u);
                ldsm2(bl, bbase + 8448u + (u32)k * 32u);
                mma16816(c, ah, bh);
                mma16816(c, al, bh);
                mma16816(c, ah, bl);
            }
            int rlo = mt * 16 + row_lo0, rhi = rlo + 8;
            int og = cb * 16 + nt * 8 + col0;
            float s0 = bnsc[og], h0 = bnsh[og];
            float s1 = bnsc[og + 1], h1 = bnsh[og + 1];
            float y0 = fmaxf(fmaf(c[0], s0, h0), 0.0f);
            float y1 = fmaxf(fmaf(c[1], s1, h1), 0.0f);
            *(float2*)(ysf + rlo * 18 + nt * 8 + col0) = make_float2(y0, y1);
            if (rhi < 136) {
                float y2 = fmaxf(fmaf(c[2], s0, h0), 0.0f);
                float y3 = fmaxf(fmaf(c[3], s1, h1), 0.0f);
                *(float2*)(ysf + rhi * 18 + nt * 8 + col0) = make_float2(y2, y3);
            }
        }
        __syncthreads();
        // coalesced store: out[(b*256 + cb*16 + ol)*8704 + t0*17 + tok]
        {
            float* op = out + (size_t)(b * 256 + cb * 16) * 8704 + (size_t)t0 * 17;
            for (int idx = tid; idx < 16 * 136; idx += 512) {
                int ol = idx / 136;
                int tok = idx - ol * 136;
                op[(size_t)ol * 8704 + tok] = ysf[tok * 18 + ol];
            }
        }
    }
}

// ---------------- launch ----------------
extern "C" void kernel_launch(void* const* d_in, const int* in_sizes, int n_in,
                              void* d_out, int out_size) {
    const float* x      = (const float*)d_in[0];
    const float* adj    = (const float*)d_in[1];
    const float* Wq     = (const float*)d_in[2];
    const float* Wk     = (const float*)d_in[3];
    const float* Wv     = (const float*)d_in[4];
    const float* adj2   = (const float*)d_in[5];
    const float* convw  = (const float*)d_in[6];
    const float* bng    = (const float*)d_in[7];
    const float* bnb    = (const float*)d_in[8];
    const float* bnm    = (const float*)d_in[9];
    const float* bnv    = (const float*)d_in[10];
    float* out = (float*)d_out;

    cudaFuncSetAttribute(gab_kernel, cudaFuncAttributeMaxDynamicSharedMemorySize, SMEM_BYTES);

    prep_kernel<<<(4 * 96 * 128 + 16 * 16 * 256 + 255) / 256, 256>>>(Wq, Wk, Wv, convw);
    gab_kernel<<<2048, 512, SMEM_BYTES>>>(x, adj, adj2, bng, bnb, bnm, bnv, out);
}

// round 13
// speedup vs baseline: 1.9503x; 1.1755x over previous
#include <cuda_runtime.h>
#include <cuda_bf16.h>
#include <cstdint>
#include <cstddef>

typedef unsigned int u32;

#define NEG_INFF (-9.0e15f)
#define BN_EPS 1e-5f

// ---------------- smem layout (bytes) ----------------
// A tiles: [136 tok][264 k] bf16, stride 528 B (ldmatrix conflict-free: 33%8==1)
#define AH_B   0u
#define AL_B   71808u          // 136*528
#define QS_B   143616u         // qs[136][36] f32 = 19584 ; also Ys[136][34] in conv
#define KS_B   163200u         // ks ; also conv weight stage (33792 B spans KS+VS)
#define VS_B   182784u
#define MB_B   202368u         // mask 4*289 f32 = 4624
#define BS_B   206992u         // qkv weight stage: 17408 B
#define BNS_B  224400u         // bn scale 256 f32
#define BNB_B  225424u
#define SMEM_BYTES 226448u

// ---------------- pre-packed bf16 weight images ----------------
// g_Bqkv[g][third][hi/lo][n*136+c]: third 0=q,1=k,2=v (32 cols each), k-stride 136
__device__ __align__(16) __nv_bfloat16 g_Bqkv[4][3][2][32 * 136];
// g_Bconv[cb][hi/lo][n*264+c]: 8 chunks of 32 outputs, k-stride 264 (K=256)
__device__ __align__(16) __nv_bfloat16 g_Bconv[8][2][32 * 264];

__global__ void prep_kernel(const float* __restrict__ Wq, const float* __restrict__ Wk,
                            const float* __restrict__ Wv, const float* __restrict__ cw) {
    int i = blockIdx.x * blockDim.x + threadIdx.x;
    if (i < 4 * 96 * 128) {
        int g = i / 12288; int r = i - g * 12288;
        int n = r >> 7, c = r & 127;
        int third = n >> 5, nl = n & 31;
        int h = g * 4 + (nl >> 3), e = nl & 7;
        const float* W = (third == 0) ? Wq : (third == 1 ? Wk : Wv);
        float w = W[h * 1024 + c * 8 + e];        // W[h][c][e] (16,128,8)
        __nv_bfloat16 hi = __float2bfloat16_rn(w);
        __nv_bfloat16 lo = __float2bfloat16_rn(w - __bfloat162float(hi));
        g_Bqkv[g][third][0][nl * 136 + c] = hi;
        g_Bqkv[g][third][1][nl * 136 + c] = lo;
    } else {
        int j = i - 4 * 96 * 128;
        if (j < 256 * 256) {
            int o = j >> 8, c = j & 255;
            int cb = o >> 5, n = o & 31;
            float w = cw[o * 256 + c];
            __nv_bfloat16 hi = __float2bfloat16_rn(w);
            __nv_bfloat16 lo = __float2bfloat16_rn(w - __bfloat162float(hi));
            g_Bconv[cb][0][n * 264 + c] = hi;
            g_Bconv[cb][1][n * 264 + c] = lo;
        }
    }
}

// ---------------- warp mma helpers ----------------
__device__ __forceinline__ u32 smem_u32(const void* p) {
    u32 a;
    asm("{ .reg .u64 t; cvta.to.shared.u64 t, %1; cvt.u32.u64 %0, t; }" : "=r"(a) : "l"(p));
    return a;
}
__device__ __forceinline__ void ldsm4(u32* r, u32 a) {
    asm volatile("ldmatrix.sync.aligned.m8n8.x4.shared.b16 {%0,%1,%2,%3}, [%4];"
                 : "=r"(r[0]), "=r"(r[1]), "=r"(r[2]), "=r"(r[3]) : "r"(a));
}
__device__ __forceinline__ void ldsm2(u32* r, u32 a) {
    asm volatile("ldmatrix.sync.aligned.m8n8.x2.shared.b16 {%0,%1}, [%2];"
                 : "=r"(r[0]), "=r"(r[1]) : "r"(a));
}
__device__ __forceinline__ void mma16816(float* c, const u32* a, const u32* b) {
    asm volatile(
        "mma.sync.aligned.m16n8k16.row.col.f32.bf16.bf16.f32 "
        "{%0,%1,%2,%3}, {%4,%5,%6,%7}, {%8,%9}, {%0,%1,%2,%3};"
        : "+f"(c[0]), "+f"(c[1]), "+f"(c[2]), "+f"(c[3])
        : "r"(a[0]), "r"(a[1]), "r"(a[2]), "r"(a[3]), "r"(b[0]), "r"(b[1]));
}
__device__ __forceinline__ void split2(float a, float b, u32& hu, u32& lu) {
    __nv_bfloat16 ha = __float2bfloat16_rn(a), hb = __float2bfloat16_rn(b);
    float ra = a - __bfloat162float(ha), rb = b - __bfloat162float(hb);
    __nv_bfloat16 la = __float2bfloat16_rn(ra), lb = __float2bfloat16_rn(rb);
    hu = (u32)__bfloat16_as_ushort(ha) | ((u32)__bfloat16_as_ushort(hb) << 16);
    lu = (u32)__bfloat16_as_ushort(la) | ((u32)__bfloat16_as_ushort(lb) << 16);
}

extern __shared__ __align__(16) unsigned char sp[];

__global__ void __launch_bounds__(512, 1)
gab_kernel(const float* __restrict__ x, const float* __restrict__ adj,
           const float* __restrict__ adj2,
           const float* __restrict__ bng, const float* __restrict__ bnbv,
           const float* __restrict__ bnm, const float* __restrict__ bnv,
           float* __restrict__ out) {
    const u32 sb = smem_u32(sp);
    const int b  = blockIdx.x >> 6;
    const int tb = blockIdx.x & 63;
    const int t0 = tb * 8;
    const int tid  = threadIdx.x;
    const int lane = tid & 31;
    const int wid  = tid >> 5;

    // ---- register prefetch of first weight stage (overlaps Phase A) ----
    uint4 pf0, pf1, pf2, pf3, pf4;
    int pcnt = 1088;                      // uint4 count currently in regs
    {
        const uint4* src = (const uint4*)&g_Bqkv[0][0][0][0];
        pf0 = __ldg(src + tid);
        if (tid + 512 < 1088)  pf1 = __ldg(src + tid + 512);
        if (tid + 1024 < 1088) pf2 = __ldg(src + tid + 1024);
    }

    // ---- Phase A: load X, bf16-split into A_hi/A_lo [tok][c] (c: 0..127) ----
    {
        const float* xb = x + (size_t)b * 128 * 8704 + (size_t)t0 * 17;
        for (int d4 = wid; d4 < 32; d4 += 16) {
            const float* s0 = xb + (size_t)(d4 * 4 + 0) * 8704;
            const float* s1 = xb + (size_t)(d4 * 4 + 1) * 8704;
            const float* s2 = xb + (size_t)(d4 * 4 + 2) * 8704;
            const float* s3 = xb + (size_t)(d4 * 4 + 3) * 8704;
            for (int tok = lane; tok < 136; tok += 32) {
                float v0 = s0[tok], v1 = s1[tok], v2 = s2[tok], v3 = s3[tok];
                u32 h01, l01, h23, l23;
                split2(v0, v1, h01, l01);
                split2(v2, v3, h23, l23);
                u32 off = (u32)tok * 528u + (u32)d4 * 8u;
                *(uint2*)(sp + AH_B + off) = make_uint2(h01, h23);
                *(uint2*)(sp + AL_B + off) = make_uint2(l01, l23);
            }
        }
    }
    // ---- BN fold ----
    if (tid < 256) {
        float sc = bng[tid] * rsqrtf(bnv[tid] + BN_EPS);
        ((float*)(sp + BNS_B))[tid] = sc;
        ((float*)(sp + BNB_B))[tid] = bnbv[tid] - bnm[tid] * sc;
    }

    const float inv_s = 0.3535533905932738f;   // 1/sqrt(8)
    float* qsf = (float*)(sp + QS_B);
    float* ksf = (float*)(sp + KS_B);
    float* vsf = (float*)(sp + VS_B);
    float* mbf = (float*)(sp + MB_B);
    const int row_lo0 = (lane >> 2);
    const int col0 = (lane & 3) * 2;

    // ---- Phase B: 4 head-groups; per group: 3 thirds (q/k/v), then attention ----
    for (int g = 0; g < 4; ++g) {
        for (int third = 0; third < 3; ++third) {
            __syncthreads();   // prev BS reads done / Phase A visible
            // commit prefetched stage to BS
            {
                uint4* dst = (uint4*)(sp + BS_B);
                dst[tid] = pf0;
                if (tid + 512 < pcnt)  dst[tid + 512] = pf1;
                if (tid + 1024 < pcnt) dst[tid + 1024] = pf2;
            }
            // prefetch next stage
            {
                int st = g * 3 + third;
                if (st < 11) {
                    int ns = st + 1;
                    const uint4* nsrc = (const uint4*)&g_Bqkv[ns / 3][ns % 3][0][0];
                    pf0 = __ldg(nsrc + tid);
                    if (tid + 512 < 1088)  pf1 = __ldg(nsrc + tid + 512);
                    if (tid + 1024 < 1088) pf2 = __ldg(nsrc + tid + 1024);
                    pcnt = 1088;
                } else {
                    const uint4* nsrc = (const uint4*)&g_Bconv[0][0][0];
                    pf0 = __ldg(nsrc + tid);
                    pf1 = __ldg(nsrc + tid + 512);
                    pf2 = __ldg(nsrc + tid + 1024);
                    pf3 = __ldg(nsrc + tid + 1536);
                    if (tid + 2048 < 2112) pf4 = __ldg(nsrc + tid + 2048);
                    pcnt = 2112;
                }
            }
            if (third == 0) {
                for (int idx = tid; idx < 4 * 289; idx += 512) {
                    int hl = idx / 289, r = idx - hl * 289;
                    int n = r / 17, m = r - n * 17;
                    int hh = g * 4 + hl;
                    float a = 0.5f * (adj[n * 17 + m] + adj[m * 17 + n])
                            + 0.5f * (adj2[hh * 289 + n * 17 + m] + adj2[hh * 289 + m * 17 + n]);
                    mbf[idx] = (a > 0.0f) ? 0.0f : NEG_INFF;
                }
            }
            __syncthreads();

            // 18 units = (mt 0..8, n-half 0..1)
            for (int u = wid; u < 18; u += 16) {
                int mt = u >> 1, nh = u & 1;
                u32 abase = sb + AH_B + (u32)(mt * 16 + (lane & 15)) * 528u + (u32)((lane >> 4) * 16);
                u32 albase = abase + (AL_B - AH_B);
                u32 bbase = sb + BS_B + (u32)(lane & 7) * 272u + (u32)(((lane >> 3) & 1) * 16);
                float c[2][4];
#pragma unroll
                for (int nt = 0; nt < 2; ++nt)
#pragma unroll
                    for (int e = 0; e < 4; ++e) c[nt][e] = 0.f;
#pragma unroll
                for (int k = 0; k < 8; ++k) {
                    u32 ah[4], al[4];
                    ldsm4(ah, abase + (u32)k * 32u);
                    ldsm4(al, albase + (u32)k * 32u);
#pragma unroll
                    for (int nt = 0; nt < 2; ++nt) {
                        int ncol = nh * 2 + nt;
                        u32 bh[2], bl[2];
                        ldsm2(bh, bbase + (u32)(ncol * 8) * 272u + (u32)k * 32u);
                        ldsm2(bl, bbase + 8704u + (u32)(ncol * 8) * 272u + (u32)k * 32u);
                        mma16816(c[nt], ah, bh);
                        mma16816(c[nt], al, bh);
                        mma16816(c[nt], ah, bl);
                    }
                }
                float* buf = (third == 0) ? qsf : (third == 1 ? ksf : vsf);
                int rlo = mt * 16 + row_lo0, rhi = rlo + 8;
#pragma unroll
                for (int nt = 0; nt < 2; ++nt) {
                    int oc = (nh * 2 + nt) * 8 + col0;
                    *(float2*)(buf + rlo * 36 + oc) = make_float2(c[nt][0], c[nt][1]);
                    if (rhi < 136)
                        *(float2*)(buf + rhi * 36 + oc) = make_float2(c[nt][2], c[nt][3]);
                }
            }
        }
        __syncthreads();   // q/k/v epilogues visible

        // ---- attention (fp32 scalar, 544 rows) ----
        for (int r = tid; r < 544; r += 512) {
            int hl  = r / 136;
            int tok = r - hl * 136;
            int tl  = tok / 17;
            int n   = tok - tl * 17;
            const float* qp = qsf + tok * 36 + hl * 8;
            const float* kb = ksf + (tl * 17) * 36 + hl * 8;
            const float* vb = vsf + (tl * 17) * 36 + hl * 8;
            const float* mb = mbf + hl * 289 + n * 17;
            float4 q0 = *(const float4*)(qp);
            float4 q1 = *(const float4*)(qp + 4);
            float ev[17];
            float mx = -3.4e38f;
#pragma unroll
            for (int m = 0; m < 17; ++m) {
                const float* kp = kb + m * 36;
                float4 k0 = *(const float4*)(kp);
                float4 k1 = *(const float4*)(kp + 4);
                float d0 = q0.x * k0.x;
                d0 = fmaf(q0.y, k0.y, d0); d0 = fmaf(q0.z, k0.z, d0); d0 = fmaf(q0.w, k0.w, d0);
                d0 = fmaf(q1.x, k1.x, d0); d0 = fmaf(q1.y, k1.y, d0);
                d0 = fmaf(q1.z, k1.z, d0); d0 = fmaf(q1.w, k1.w, d0);
                ev[m] = fmaf(d0, inv_s, mb[m]);
                mx = fmaxf(mx, ev[m]);
            }
            float s = 0.f;
#pragma unroll
            for (int m = 0; m < 17; ++m) { ev[m] = __expf(ev[m] - mx); s += ev[m]; }
            float inv = __fdividef(1.0f, s);
            float a0x = 0.f, a0y = 0.f, a0z = 0.f, a0w = 0.f;
            float a1x = 0.f, a1y = 0.f, a1z = 0.f, a1w = 0.f;
#pragma unroll
            for (int m = 0; m < 17; ++m) {
                const float* vp = vb + m * 36;
                float4 v0 = *(const float4*)(vp);
                float4 v1 = *(const float4*)(vp + 4);
                float pm = ev[m];
                a0x = fmaf(pm, v0.x, a0x); a0y = fmaf(pm, v0.y, a0y);
                a0z = fmaf(pm, v0.z, a0z); a0w = fmaf(pm, v0.w, a0w);
                a1x = fmaf(pm, v1.x, a1x); a1y = fmaf(pm, v1.y, a1y);
                a1z = fmaf(pm, v1.z, a1z); a1w = fmaf(pm, v1.w, a1w);
            }
            u32 h0, l0, h1, l1, h2, l2, h3, l3;
            split2(a0x * inv, a0y * inv, h0, l0);
            split2(a0z * inv, a0w * inv, h1, l1);
            split2(a1x * inv, a1y * inv, h2, l2);
            split2(a1z * inv, a1w * inv, h3, l3);
            u32 off = (u32)tok * 528u + 256u + (u32)g * 64u + (u32)hl * 16u;
            *(uint4*)(sp + AH_B + off) = make_uint4(h0, h1, h2, h3);
            *(uint4*)(sp + AL_B + off) = make_uint4(l0, l1, l2, l3);
        }
    }

    // ---- Phase C: conv1x1 via MMA (K=256), 8 chunks of 32 outputs ----
    const float* bnsc = (const float*)(sp + BNS_B);
    const float* bnsh = (const float*)(sp + BNB_B);
    float* ysf = (float*)(sp + QS_B);   // Ys[136][34]
    const u32 CW = KS_B;                // conv weight stage spans KS+VS region
    for (int cb = 0; cb < 8; ++cb) {
        __syncthreads();   // prev reads done; attention writes visible (cb=0)
        {
            uint4* dst = (uint4*)(sp + CW);
            dst[tid] = pf0;
            dst[tid + 512] = pf1;
            dst[tid + 1024] = pf2;
            dst[tid + 1536] = pf3;
            if (tid + 2048 < 2112) dst[tid + 2048] = pf4;
        }
        if (cb < 7) {
            const uint4* nsrc = (const uint4*)&g_Bconv[cb + 1][0][0];
            pf0 = __ldg(nsrc + tid);
            pf1 = __ldg(nsrc + tid + 512);
            pf2 = __ldg(nsrc + tid + 1024);
            pf3 = __ldg(nsrc + tid + 1536);
            if (tid + 2048 < 2112) pf4 = __ldg(nsrc + tid + 2048);
        }
        __syncthreads();

        // 18 units = (mt 0..8, nh 0..1); nh covers 2 n-tiles of the 32-output chunk
        for (int u = wid; u < 18; u += 16) {
            int mt = u >> 1, nh = u & 1;
            u32 abase = sb + AH_B + (u32)(mt * 16 + (lane & 15)) * 528u + (u32)((lane >> 4) * 16);
            u32 albase = abase + (AL_B - AH_B);
            u32 bbase = sb + CW + (u32)(lane & 7) * 528u + (u32)(((lane >> 3) & 1) * 16);
            float c[2][4];
#pragma unroll
            for (int nt = 0; nt < 2; ++nt)
#pragma unroll
                for (int e = 0; e < 4; ++e) c[nt][e] = 0.f;
#pragma unroll 4
            for (int k = 0; k < 16; ++k) {
                u32 ah[4], al[4];
                ldsm4(ah, abase + (u32)k * 32u);
                ldsm4(al, albase + (u32)k * 32u);
#pragma unroll
                for (int nt = 0; nt < 2; ++nt) {
                    int ncol = nh * 2 + nt;
                    u32 bh[2], bl[2];
                    ldsm2(bh, bbase + (u32)(ncol * 8) * 528u + (u32)k * 32u);
                    ldsm2(bl, bbase + 16896u + (u32)(ncol * 8) * 528u + (u32)k * 32u);
                    mma16816(c[nt], ah, bh);
                    mma16816(c[nt], al, bh);
                    mma16816(c[nt], ah, bl);
                }
            }
            int rlo = mt * 16 + row_lo0, rhi = rlo + 8;
#pragma unroll
            for (int nt = 0; nt < 2; ++nt) {
                int lc = (nh * 2 + nt) * 8 + col0;
                int og = cb * 32 + lc;
                float s0 = bnsc[og], h0 = bnsh[og];
                float s1 = bnsc[og + 1], h1 = bnsh[og + 1];
                float y0 = fmaxf(fmaf(c[nt][0], s0, h0), 0.0f);
                float y1 = fmaxf(fmaf(c[nt][1], s1, h1), 0.0f);
                *(float2*)(ysf + rlo * 34 + lc) = make_float2(y0, y1);
                if (rhi < 136) {
                    float y2 = fmaxf(fmaf(c[nt][2], s0, h0), 0.0f);
                    float y3 = fmaxf(fmaf(c[nt][3], s1, h1), 0.0f);
                    *(float2*)(ysf + rhi * 34 + lc) = make_float2(y2, y3);
                }
            }
        }
        __syncthreads();
        // coalesced store: out[(b*256 + cb*32 + ol)*8704 + t0*17 + tok]
        {
            float* op = out + (size_t)(b * 256 + cb * 32) * 8704 + (size_t)t0 * 17;
            for (int idx = tid; idx < 32 * 136; idx += 512) {
                int ol = idx / 136;
                int tok = idx - ol * 136;
                op[(size_t)ol * 8704 + tok] = ysf[tok * 34 + ol];
            }
        }
    }
}

// ---------------- launch ----------------
extern "C" void kernel_launch(void* const* d_in, const int* in_sizes, int n_in,
                              void* d_out, int out_size) {
    const float* x      = (const float*)d_in[0];
    const float* adj    = (const float*)d_in[1];
    const float* Wq     = (const float*)d_in[2];
    const float* Wk     = (const float*)d_in[3];
    const float* Wv     = (const float*)d_in[4];
    const float* adj2   = (const float*)d_in[5];
    const float* convw  = (const float*)d_in[6];
    const float* bng    = (const float*)d_in[7];
    const float* bnb    = (const float*)d_in[8];
    const float* bnm    = (const float*)d_in[9];
    const float* bnv    = (const float*)d_in[10];
    float* out = (float*)d_out;

    cudaFuncSetAttribute(gab_kernel, cudaFuncAttributeMaxDynamicSharedMemorySize, SMEM_BYTES);

    prep_kernel<<<(4 * 96 * 128 + 256 * 256 + 255) / 256, 256>>>(Wq, Wk, Wv, convw);
    gab_kernel<<<2048, 512, SMEM_BYTES>>>(x, adj, adj2, bng, bnb, bnm, bnv, out);
}

// round 14
// speedup vs baseline: 2.2534x; 1.1554x over previous
#include <cuda_runtime.h>
#include <cuda_bf16.h>
#include <cstdint>
#include <cstddef>

typedef unsigned int u32;

#define NEG_INFF (-9.0e15f)
#define BN_EPS 1e-5f

// ---------------- smem layout (bytes) ----------------
// A tiles: [136 tok][264 k] bf16, stride 528 B (ldmatrix conflict-free: 33%8==1)
#define AH_B   0u
#define AL_B   71808u          // 136*528
#define QS_B   143616u         // qs[136][36] f32 ; conv: weight stage base (67584 B spans QS..211200)
#define KS_B   163200u
#define VS_B   182784u
#define MB_B   202368u         // mask 4*289 f32 = 4624
#define BS_B   206992u         // qkv weight stage: 17408 B
#define BNS_B  224400u         // bn scale 256 f32
#define BNB_B  225424u
#define SMEM_BYTES 226448u

// ---------------- pre-packed bf16 weight images ----------------
// g_Bqkv[g][third][hi/lo][n*136+c]: third 0=q,1=k,2=v (32 cols each), k-stride 136
__device__ __align__(16) __nv_bfloat16 g_Bqkv[4][3][2][32 * 136];
// g_Bconv[cb][hi/lo][n*264+c]: 4 chunks of 64 outputs, k-stride 264 (K=256)
__device__ __align__(16) __nv_bfloat16 g_Bconv[4][2][64 * 264];

__global__ void prep_kernel(const float* __restrict__ Wq, const float* __restrict__ Wk,
                            const float* __restrict__ Wv, const float* __restrict__ cw) {
    int i = blockIdx.x * blockDim.x + threadIdx.x;
    if (i < 4 * 96 * 128) {
        int g = i / 12288; int r = i - g * 12288;
        int n = r >> 7, c = r & 127;
        int third = n >> 5, nl = n & 31;
        int h = g * 4 + (nl >> 3), e = nl & 7;
        const float* W = (third == 0) ? Wq : (third == 1 ? Wk : Wv);
        float w = W[h * 1024 + c * 8 + e];        // W[h][c][e] (16,128,8)
        __nv_bfloat16 hi = __float2bfloat16_rn(w);
        __nv_bfloat16 lo = __float2bfloat16_rn(w - __bfloat162float(hi));
        g_Bqkv[g][third][0][nl * 136 + c] = hi;
        g_Bqkv[g][third][1][nl * 136 + c] = lo;
    } else {
        int j = i - 4 * 96 * 128;
        if (j < 256 * 256) {
            int o = j >> 8, c = j & 255;
            int cb = o >> 6, n = o & 63;
            float w = cw[o * 256 + c];
            __nv_bfloat16 hi = __float2bfloat16_rn(w);
            __nv_bfloat16 lo = __float2bfloat16_rn(w - __bfloat162float(hi));
            g_Bconv[cb][0][n * 264 + c] = hi;
            g_Bconv[cb][1][n * 264 + c] = lo;
        }
    }
}

// ---------------- warp mma helpers ----------------
__device__ __forceinline__ u32 smem_u32(const void* p) {
    u32 a;
    asm("{ .reg .u64 t; cvta.to.shared.u64 t, %1; cvt.u32.u64 %0, t; }" : "=r"(a) : "l"(p));
    return a;
}
__device__ __forceinline__ void ldsm4(u32* r, u32 a) {
    asm volatile("ldmatrix.sync.aligned.m8n8.x4.shared.b16 {%0,%1,%2,%3}, [%4];"
                 : "=r"(r[0]), "=r"(r[1]), "=r"(r[2]), "=r"(r[3]) : "r"(a));
}
__device__ __forceinline__ void ldsm2(u32* r, u32 a) {
    asm volatile("ldmatrix.sync.aligned.m8n8.x2.shared.b16 {%0,%1}, [%2];"
                 : "=r"(r[0]), "=r"(r[1]) : "r"(a));
}
__device__ __forceinline__ void mma16816(float* c, const u32* a, const u32* b) {
    asm volatile(
        "mma.sync.aligned.m16n8k16.row.col.f32.bf16.bf16.f32 "
        "{%0,%1,%2,%3}, {%4,%5,%6,%7}, {%8,%9}, {%0,%1,%2,%3};"
        : "+f"(c[0]), "+f"(c[1]), "+f"(c[2]), "+f"(c[3])
        : "r"(a[0]), "r"(a[1]), "r"(a[2]), "r"(a[3]), "r"(b[0]), "r"(b[1]));
}
__device__ __forceinline__ void split2(float a, float b, u32& hu, u32& lu) {
    __nv_bfloat16 ha = __float2bfloat16_rn(a), hb = __float2bfloat16_rn(b);
    float ra = a - __bfloat162float(ha), rb = b - __bfloat162float(hb);
    __nv_bfloat16 la = __float2bfloat16_rn(ra), lb = __float2bfloat16_rn(rb);
    hu = (u32)__bfloat16_as_ushort(ha) | ((u32)__bfloat16_as_ushort(hb) << 16);
    lu = (u32)__bfloat16_as_ushort(la) | ((u32)__bfloat16_as_ushort(lb) << 16);
}
__device__ __forceinline__ void cpasync16(u32 dst, const void* src) {
    unsigned long long g;
    asm("cvta.to.global.u64 %0, %1;" : "=l"(g) : "l"(src));
    asm volatile("cp.async.cg.shared.global [%0], [%1], 16;" :: "r"(dst), "l"(g) : "memory");
}

extern __shared__ __align__(16) unsigned char sp[];

__global__ void __launch_bounds__(512, 1)
gab_kernel(const float* __restrict__ x, const float* __restrict__ adj,
           const float* __restrict__ adj2,
           const float* __restrict__ bng, const float* __restrict__ bnbv,
           const float* __restrict__ bnm, const float* __restrict__ bnv,
           float* __restrict__ out) {
    const u32 sb = smem_u32(sp);
    const int b  = blockIdx.x >> 6;
    const int tb = blockIdx.x & 63;
    const int t0 = tb * 8;
    const int tid  = threadIdx.x;
    const int lane = tid & 31;
    const int wid  = tid >> 5;

    // ---- register prefetch of first qkv weight stage (overlaps Phase A) ----
    uint4 pf0, pf1, pf2;
    {
        const uint4* src = (const uint4*)&g_Bqkv[0][0][0][0];
        pf0 = __ldg(src + tid);
        if (tid + 512 < 1088)  pf1 = __ldg(src + tid + 512);
        if (tid + 1024 < 1088) pf2 = __ldg(src + tid + 1024);
    }

    // ---- Phase A: load X, bf16-split into A_hi/A_lo [tok][c] (c: 0..127) ----
    {
        const float* xb = x + (size_t)b * 128 * 8704 + (size_t)t0 * 17;
        for (int d4 = wid; d4 < 32; d4 += 16) {
            const float* s0 = xb + (size_t)(d4 * 4 + 0) * 8704;
            const float* s1 = xb + (size_t)(d4 * 4 + 1) * 8704;
            const float* s2 = xb + (size_t)(d4 * 4 + 2) * 8704;
            const float* s3 = xb + (size_t)(d4 * 4 + 3) * 8704;
            for (int tok = lane; tok < 136; tok += 32) {
                float v0 = s0[tok], v1 = s1[tok], v2 = s2[tok], v3 = s3[tok];
                u32 h01, l01, h23, l23;
                split2(v0, v1, h01, l01);
                split2(v2, v3, h23, l23);
                u32 off = (u32)tok * 528u + (u32)d4 * 8u;
                *(uint2*)(sp + AH_B + off) = make_uint2(h01, h23);
                *(uint2*)(sp + AL_B + off) = make_uint2(l01, l23);
            }
        }
    }
    // ---- BN fold ----
    if (tid < 256) {
        float sc = bng[tid] * rsqrtf(bnv[tid] + BN_EPS);
        ((float*)(sp + BNS_B))[tid] = sc;
        ((float*)(sp + BNB_B))[tid] = bnbv[tid] - bnm[tid] * sc;
    }

    const float inv_s = 0.3535533905932738f;   // 1/sqrt(8)
    float* qsf = (float*)(sp + QS_B);
    float* ksf = (float*)(sp + KS_B);
    float* vsf = (float*)(sp + VS_B);
    float* mbf = (float*)(sp + MB_B);
    const int row_lo0 = (lane >> 2);
    const int col0 = (lane & 3) * 2;

    // ---- Phase B: 4 head-groups; per group: 3 thirds (q/k/v), then attention ----
    for (int g = 0; g < 4; ++g) {
        for (int third = 0; third < 3; ++third) {
            __syncthreads();   // prev BS reads done / Phase A visible
            // commit prefetched stage to BS
            {
                uint4* dst = (uint4*)(sp + BS_B);
                dst[tid] = pf0;
                if (tid + 512 < 1088)  dst[tid + 512] = pf1;
                if (tid + 1024 < 1088) dst[tid + 1024] = pf2;
            }
            // prefetch next qkv stage
            {
                int st = g * 3 + third;
                if (st < 11) {
                    int ns = st + 1;
                    const uint4* nsrc = (const uint4*)&g_Bqkv[ns / 3][ns % 3][0][0];
                    pf0 = __ldg(nsrc + tid);
                    if (tid + 512 < 1088)  pf1 = __ldg(nsrc + tid + 512);
                    if (tid + 1024 < 1088) pf2 = __ldg(nsrc + tid + 1024);
                }
            }
            if (third == 0) {
                for (int idx = tid; idx < 4 * 289; idx += 512) {
                    int hl = idx / 289, r = idx - hl * 289;
                    int n = r / 17, m = r - n * 17;
                    int hh = g * 4 + hl;
                    float a = 0.5f * (adj[n * 17 + m] + adj[m * 17 + n])
                            + 0.5f * (adj2[hh * 289 + n * 17 + m] + adj2[hh * 289 + m * 17 + n]);
                    mbf[idx] = (a > 0.0f) ? 0.0f : NEG_INFF;
                }
            }
            __syncthreads();

            // 18 units = (mt 0..8, n-half 0..1)
            for (int u = wid; u < 18; u += 16) {
                int mt = u >> 1, nh = u & 1;
                u32 abase = sb + AH_B + (u32)(mt * 16 + (lane & 15)) * 528u + (u32)((lane >> 4) * 16);
                u32 albase = abase + (AL_B - AH_B);
                u32 bbase = sb + BS_B + (u32)(lane & 7) * 272u + (u32)(((lane >> 3) & 1) * 16);
                float c[2][4];
#pragma unroll
                for (int nt = 0; nt < 2; ++nt)
#pragma unroll
                    for (int e = 0; e < 4; ++e) c[nt][e] = 0.f;
#pragma unroll
                for (int k = 0; k < 8; ++k) {
                    u32 ah[4], al[4];
                    ldsm4(ah, abase + (u32)k * 32u);
                    ldsm4(al, albase + (u32)k * 32u);
#pragma unroll
                    for (int nt = 0; nt < 2; ++nt) {
                        int ncol = nh * 2 + nt;
                        u32 bh[2], bl[2];
                        ldsm2(bh, bbase + (u32)(ncol * 8) * 272u + (u32)k * 32u);
                        ldsm2(bl, bbase + 8704u + (u32)(ncol * 8) * 272u + (u32)k * 32u);
                        mma16816(c[nt], ah, bh);
                        mma16816(c[nt], al, bh);
                        mma16816(c[nt], ah, bl);
                    }
                }
                float* buf = (third == 0) ? qsf : (third == 1 ? ksf : vsf);
                int rlo = mt * 16 + row_lo0, rhi = rlo + 8;
#pragma unroll
                for (int nt = 0; nt < 2; ++nt) {
                    int oc = (nh * 2 + nt) * 8 + col0;
                    *(float2*)(buf + rlo * 36 + oc) = make_float2(c[nt][0], c[nt][1]);
                    if (rhi < 136)
                        *(float2*)(buf + rhi * 36 + oc) = make_float2(c[nt][2], c[nt][3]);
                }
            }
        }
        __syncthreads();   // q/k/v epilogues visible

        // ---- attention (fp32 scalar, 544 rows) ----
        for (int r = tid; r < 544; r += 512) {
            int hl  = r / 136;
            int tok = r - hl * 136;
            int tl  = tok / 17;
            int n   = tok - tl * 17;
            const float* qp = qsf + tok * 36 + hl * 8;
            const float* kb = ksf + (tl * 17) * 36 + hl * 8;
            const float* vb = vsf + (tl * 17) * 36 + hl * 8;
            const float* mb = mbf + hl * 289 + n * 17;
            float4 q0 = *(const float4*)(qp);
            float4 q1 = *(const float4*)(qp + 4);
            float ev[17];
            float mx = -3.4e38f;
#pragma unroll
            for (int m = 0; m < 17; ++m) {
                const float* kp = kb + m * 36;
                float4 k0 = *(const float4*)(kp);
                float4 k1 = *(const float4*)(kp + 4);
                float d0 = q0.x * k0.x;
                d0 = fmaf(q0.y, k0.y, d0); d0 = fmaf(q0.z, k0.z, d0); d0 = fmaf(q0.w, k0.w, d0);
                d0 = fmaf(q1.x, k1.x, d0); d0 = fmaf(q1.y, k1.y, d0);
                d0 = fmaf(q1.z, k1.z, d0); d0 = fmaf(q1.w, k1.w, d0);
                ev[m] = fmaf(d0, inv_s, mb[m]);
                mx = fmaxf(mx, ev[m]);
            }
            float s = 0.f;
#pragma unroll
            for (int m = 0; m < 17; ++m) { ev[m] = __expf(ev[m] - mx); s += ev[m]; }
            float inv = __fdividef(1.0f, s);
            float a0x = 0.f, a0y = 0.f, a0z = 0.f, a0w = 0.f;
            float a1x = 0.f, a1y = 0.f, a1z = 0.f, a1w = 0.f;
#pragma unroll
            for (int m = 0; m < 17; ++m) {
                const float* vp = vb + m * 36;
                float4 v0 = *(const float4*)(vp);
                float4 v1 = *(const float4*)(vp + 4);
                float pm = ev[m];
                a0x = fmaf(pm, v0.x, a0x); a0y = fmaf(pm, v0.y, a0y);
                a0z = fmaf(pm, v0.z, a0z); a0w = fmaf(pm, v0.w, a0w);
                a1x = fmaf(pm, v1.x, a1x); a1y = fmaf(pm, v1.y, a1y);
                a1z = fmaf(pm, v1.z, a1z); a1w = fmaf(pm, v1.w, a1w);
            }
            u32 h0, l0, h1, l1, h2, l2, h3, l3;
            split2(a0x * inv, a0y * inv, h0, l0);
            split2(a0z * inv, a0w * inv, h1, l1);
            split2(a1x * inv, a1y * inv, h2, l2);
            split2(a1z * inv, a1w * inv, h3, l3);
            u32 off = (u32)tok * 528u + 256u + (u32)g * 64u + (u32)hl * 16u;
            *(uint4*)(sp + AH_B + off) = make_uint4(h0, h1, h2, h3);
            *(uint4*)(sp + AL_B + off) = make_uint4(l0, l1, l2, l3);
        }
    }

    // ---- Phase C: conv1x1 via MMA (K=256), 4 chunks of 64 outputs, direct STG ----
    const float* bnsc = (const float*)(sp + BNS_B);
    const float* bnsh = (const float*)(sp + BNB_B);
    const u32 CW = QS_B;                // conv weight stage spans QS..(QS+67584)
    for (int cb = 0; cb < 4; ++cb) {
        __syncthreads();   // prev stage ldsm reads done; attention reads done (cb=0)
        {
            const char* src = (const char*)&g_Bconv[cb][0][0];
            for (int j = tid; j < 4224; j += 512)
                cpasync16(sb + CW + (u32)j * 16u, src + (size_t)j * 16);
            asm volatile("cp.async.commit_group;" ::: "memory");
            asm volatile("cp.async.wait_group 0;" ::: "memory");
        }
        __syncthreads();   // weights visible to all

        // 18 units = (mt 0..8, nh 0..1); nh covers 4 n-tiles (32 outputs)
        for (int u = wid; u < 18; u += 16) {
            int mt = u >> 1, nh = u & 1;
            u32 abase = sb + AH_B + (u32)(mt * 16 + (lane & 15)) * 528u + (u32)((lane >> 4) * 16);
            u32 albase = abase + (AL_B - AH_B);
            u32 bb0 = sb + CW + (u32)(lane & 7) * 528u + (u32)(((lane >> 3) & 1) * 16);
            float c[4][4];
#pragma unroll
            for (int nt = 0; nt < 4; ++nt)
#pragma unroll
                for (int e = 0; e < 4; ++e) c[nt][e] = 0.f;
#pragma unroll 4
            for (int k = 0; k < 16; ++k) {
                u32 ah[4], al[4];
                ldsm4(ah, abase + (u32)k * 32u);
                ldsm4(al, albase + (u32)k * 32u);
#pragma unroll
                for (int nt = 0; nt < 4; ++nt) {
                    int ncol = nh * 4 + nt;
                    u32 bh[2], bl[2];
                    ldsm2(bh, bb0 + (u32)(ncol * 8) * 528u + (u32)k * 32u);
                    ldsm2(bl, bb0 + 33792u + (u32)(ncol * 8) * 528u + (u32)k * 32u);
                    mma16816(c[nt], ah, bh);
                    mma16816(c[nt], al, bh);
                    mma16816(c[nt], ah, bl);
                }
            }
            // BN + ReLU + direct store
            int rlo = mt * 16 + row_lo0, rhi = rlo + 8;
#pragma unroll
            for (int nt = 0; nt < 4; ++nt) {
                int og = cb * 64 + nh * 32 + nt * 8 + col0;
                float s0 = bnsc[og], h0 = bnsh[og];
                float s1 = bnsc[og + 1], h1 = bnsh[og + 1];
                float* op0 = out + (size_t)(b * 256 + og) * 8704 + (size_t)t0 * 17;
                float* op1 = op0 + 8704;
                op0[rlo] = fmaxf(fmaf(c[nt][0], s0, h0), 0.0f);
                op1[rlo] = fmaxf(fmaf(c[nt][1], s1, h1), 0.0f);
                if (rhi < 136) {
                    op0[rhi] = fmaxf(fmaf(c[nt][2], s0, h0), 0.0f);
                    op1[rhi] = fmaxf(fmaf(c[nt][3], s1, h1), 0.0f);
                }
            }
        }
    }
}

// ---------------- launch ----------------
extern "C" void kernel_launch(void* const* d_in, const int* in_sizes, int n_in,
                              void* d_out, int out_size) {
    const float* x      = (const float*)d_in[0];
    const float* adj    = (const float*)d_in[1];
    const float* Wq     = (const float*)d_in[2];
    const float* Wk     = (const float*)d_in[3];
    const float* Wv     = (const float*)d_in[4];
    const float* adj2   = (const float*)d_in[5];
    const float* convw  = (const float*)d_in[6];
    const float* bng    = (const float*)d_in[7];
    const float* bnb    = (const float*)d_in[8];
    const float* bnm    = (const float*)d_in[9];
    const float* bnv    = (const float*)d_in[10];
    float* out = (float*)d_out;

    cudaFuncSetAttribute(gab_kernel, cudaFuncAttributeMaxDynamicSharedMemorySize, SMEM_BYTES);

    prep_kernel<<<(4 * 96 * 128 + 256 * 256 + 255) / 256, 256>>>(Wq, Wk, Wv, convw);
    gab_kernel<<<2048, 512, SMEM_BYTES>>>(x, adj, adj2, bng, bnb, bnm, bnv, out);
}

// round 15
// speedup vs baseline: 2.6918x; 1.1945x over previous
#include <cuda_runtime.h>
#include <cuda_fp16.h>
#include <cstdint>
#include <cstddef>

typedef unsigned int u32;

#define NEG_INFF (-9.0e15f)
#define BN_EPS 1e-5f

// ---------------- smem layout (bytes) ----------------
// A tiles: [136 tok][264 k] fp16, stride 528 B (ldmatrix conflict-free: 33%8==1)
#define AH_B   0u
#define AL_B   71808u          // 136*528
#define QS_B   143616u         // qs[136][36] f32 ; conv: weight stage base (33792 B spans QS..177408)
#define KS_B   163200u
#define VS_B   182784u
#define MB_B   202368u         // mask 4*289 f32 = 4624
#define BS_B   206992u         // qkv weight stage: 8704 B
#define BNS_B  224400u         // bn scale 256 f32
#define BNB_B  225424u
#define SMEM_BYTES 226448u

// ---------------- pre-packed fp16 weight images (single precision level, no split) ----------------
// g_Bqkv[g][third][n*136+c]: third 0=q,1=k,2=v (32 cols each), k-stride 136 halves (272 B rows)
__device__ __align__(16) __half g_Bqkv[4][3][32 * 136];
// g_Bconv[cb][n*264+c]: 4 chunks of 64 outputs, k-stride 264 halves (528 B rows), K=256
__device__ __align__(16) __half g_Bconv[4][64 * 264];

__global__ void prep_kernel(const float* __restrict__ Wq, const float* __restrict__ Wk,
                            const float* __restrict__ Wv, const float* __restrict__ cw) {
    int i = blockIdx.x * blockDim.x + threadIdx.x;
    if (i < 4 * 96 * 128) {
        int g = i / 12288; int r = i - g * 12288;
        int n = r >> 7, c = r & 127;
        int third = n >> 5, nl = n & 31;
        int h = g * 4 + (nl >> 3), e = nl & 7;
        const float* W = (third == 0) ? Wq : (third == 1 ? Wk : Wv);
        float w = W[h * 1024 + c * 8 + e];        // W[h][c][e] (16,128,8)
        g_Bqkv[g][third][nl * 136 + c] = __float2half_rn(w);
    } else {
        int j = i - 4 * 96 * 128;
        if (j < 256 * 256) {
            int o = j >> 8, c = j & 255;
            int cb = o >> 6, n = o & 63;
            g_Bconv[cb][n * 264 + c] = __float2half_rn(cw[o * 256 + c]);
        }
    }
}

// ---------------- warp mma helpers ----------------
__device__ __forceinline__ u32 smem_u32(const void* p) {
    u32 a;
    asm("{ .reg .u64 t; cvta.to.shared.u64 t, %1; cvt.u32.u64 %0, t; }" : "=r"(a) : "l"(p));
    return a;
}
__device__ __forceinline__ void ldsm4(u32* r, u32 a) {
    asm volatile("ldmatrix.sync.aligned.m8n8.x4.shared.b16 {%0,%1,%2,%3}, [%4];"
                 : "=r"(r[0]), "=r"(r[1]), "=r"(r[2]), "=r"(r[3]) : "r"(a));
}
__device__ __forceinline__ void ldsm2(u32* r, u32 a) {
    asm volatile("ldmatrix.sync.aligned.m8n8.x2.shared.b16 {%0,%1}, [%2];"
                 : "=r"(r[0]), "=r"(r[1]) : "r"(a));
}
__device__ __forceinline__ void mma16816(float* c, const u32* a, const u32* b) {
    asm volatile(
        "mma.sync.aligned.m16n8k16.row.col.f32.f16.f16.f32 "
        "{%0,%1,%2,%3}, {%4,%5,%6,%7}, {%8,%9}, {%0,%1,%2,%3};"
        : "+f"(c[0]), "+f"(c[1]), "+f"(c[2]), "+f"(c[3])
        : "r"(a[0]), "r"(a[1]), "r"(a[2]), "r"(a[3]), "r"(b[0]), "r"(b[1]));
}
// split two floats into fp16 hi and fp16 residual (packed as half2 words)
__device__ __forceinline__ void split2h(float a, float b, u32& hu, u32& lu) {
    __half ha = __float2half_rn(a), hb = __float2half_rn(b);
    float ra = a - __half2float(ha), rb = b - __half2float(hb);
    __half la = __float2half_rn(ra), lb = __float2half_rn(rb);
    hu = (u32)__half_as_ushort(ha) | ((u32)__half_as_ushort(hb) << 16);
    lu = (u32)__half_as_ushort(la) | ((u32)__half_as_ushort(lb) << 16);
}
__device__ __forceinline__ void cpasync16(u32 dst, const void* src) {
    unsigned long long g;
    asm("cvta.to.global.u64 %0, %1;" : "=l"(g) : "l"(src));
    asm volatile("cp.async.cg.shared.global [%0], [%1], 16;" :: "r"(dst), "l"(g) : "memory");
}

extern __shared__ __align__(16) unsigned char sp[];

__global__ void __launch_bounds__(512, 1)
gab_kernel(const float* __restrict__ x, const float* __restrict__ adj,
           const float* __restrict__ adj2,
           const float* __restrict__ bng, const float* __restrict__ bnbv,
           const float* __restrict__ bnm, const float* __restrict__ bnv,
           float* __restrict__ out) {
    const u32 sb = smem_u32(sp);
    const int b  = blockIdx.x >> 6;
    const int tb = blockIdx.x & 63;
    const int t0 = tb * 8;
    const int tid  = threadIdx.x;
    const int lane = tid & 31;
    const int wid  = tid >> 5;

    // ---- register prefetch of first qkv weight stage (8704 B = 544 uint4) ----
    uint4 pf0, pf1;
    {
        const uint4* src = (const uint4*)&g_Bqkv[0][0][0];
        pf0 = __ldg(src + tid);
        if (tid < 32) pf1 = __ldg(src + tid + 512);
    }

    // ---- Phase A: load X, fp16-split into A_hi/A_lo [tok][c] (c: 0..127) ----
    {
        const float* xb = x + (size_t)b * 128 * 8704 + (size_t)t0 * 17;
        for (int d4 = wid; d4 < 32; d4 += 16) {
            const float* s0 = xb + (size_t)(d4 * 4 + 0) * 8704;
            const float* s1 = xb + (size_t)(d4 * 4 + 1) * 8704;
            const float* s2 = xb + (size_t)(d4 * 4 + 2) * 8704;
            const float* s3 = xb + (size_t)(d4 * 4 + 3) * 8704;
            for (int tok = lane; tok < 136; tok += 32) {
                float v0 = s0[tok], v1 = s1[tok], v2 = s2[tok], v3 = s3[tok];
                u32 h01, l01, h23, l23;
                split2h(v0, v1, h01, l01);
                split2h(v2, v3, h23, l23);
                u32 off = (u32)tok * 528u + (u32)d4 * 8u;
                *(uint2*)(sp + AH_B + off) = make_uint2(h01, h23);
                *(uint2*)(sp + AL_B + off) = make_uint2(l01, l23);
            }
        }
    }
    // ---- BN fold ----
    if (tid < 256) {
        float sc = bng[tid] * rsqrtf(bnv[tid] + BN_EPS);
        ((float*)(sp + BNS_B))[tid] = sc;
        ((float*)(sp + BNB_B))[tid] = bnbv[tid] - bnm[tid] * sc;
    }

    const float inv_s = 0.3535533905932738f;   // 1/sqrt(8)
    float* qsf = (float*)(sp + QS_B);
    float* ksf = (float*)(sp + KS_B);
    float* vsf = (float*)(sp + VS_B);
    float* mbf = (float*)(sp + MB_B);
    const int row_lo0 = (lane >> 2);
    const int col0 = (lane & 3) * 2;

    // ---- Phase B: 4 head-groups; per group: 3 thirds (q/k/v), then attention ----
    for (int g = 0; g < 4; ++g) {
        for (int third = 0; third < 3; ++third) {
            __syncthreads();   // prev BS reads done / Phase A visible
            // commit prefetched stage to BS
            {
                uint4* dst = (uint4*)(sp + BS_B);
                dst[tid] = pf0;
                if (tid < 32) dst[tid + 512] = pf1;
            }
            // prefetch next qkv stage
            {
                int st = g * 3 + third;
                if (st < 11) {
                    int ns = st + 1;
                    const uint4* nsrc = (const uint4*)&g_Bqkv[ns / 3][ns % 3][0];
                    pf0 = __ldg(nsrc + tid);
                    if (tid < 32) pf1 = __ldg(nsrc + tid + 512);
                }
            }
            if (third == 0) {
                for (int idx = tid; idx < 4 * 289; idx += 512) {
                    int hl = idx / 289, r = idx - hl * 289;
                    int n = r / 17, m = r - n * 17;
                    int hh = g * 4 + hl;
                    float a = 0.5f * (adj[n * 17 + m] + adj[m * 17 + n])
                            + 0.5f * (adj2[hh * 289 + n * 17 + m] + adj2[hh * 289 + m * 17 + n]);
                    mbf[idx] = (a > 0.0f) ? 0.0f : NEG_INFF;
                }
            }
            __syncthreads();

            // 18 units = (mt 0..8, n-half 0..1)
            for (int u = wid; u < 18; u += 16) {
                int mt = u >> 1, nh = u & 1;
                u32 abase = sb + AH_B + (u32)(mt * 16 + (lane & 15)) * 528u + (u32)((lane >> 4) * 16);
                u32 albase = abase + (AL_B - AH_B);
                u32 bbase = sb + BS_B + (u32)(lane & 7) * 272u + (u32)(((lane >> 3) & 1) * 16);
                float c[2][4];
#pragma unroll
                for (int nt = 0; nt < 2; ++nt)
#pragma unroll
                    for (int e = 0; e < 4; ++e) c[nt][e] = 0.f;
#pragma unroll
                for (int k = 0; k < 8; ++k) {
                    u32 ah[4], al[4];
                    ldsm4(ah, abase + (u32)k * 32u);
                    ldsm4(al, albase + (u32)k * 32u);
#pragma unroll
                    for (int nt = 0; nt < 2; ++nt) {
                        int ncol = nh * 2 + nt;
                        u32 bh[2];
                        ldsm2(bh, bbase + (u32)(ncol * 8) * 272u + (u32)k * 32u);
                        mma16816(c[nt], ah, bh);
                        mma16816(c[nt], al, bh);
                    }
                }
                float* buf = (third == 0) ? qsf : (third == 1 ? ksf : vsf);
                int rlo = mt * 16 + row_lo0, rhi = rlo + 8;
#pragma unroll
                for (int nt = 0; nt < 2; ++nt) {
                    int oc = (nh * 2 + nt) * 8 + col0;
                    *(float2*)(buf + rlo * 36 + oc) = make_float2(c[nt][0], c[nt][1]);
                    if (rhi < 136)
                        *(float2*)(buf + rhi * 36 + oc) = make_float2(c[nt][2], c[nt][3]);
                }
            }
        }
        __syncthreads();   // q/k/v epilogues visible

        // ---- attention (fp32 scalar, 544 rows) ----
        for (int r = tid; r < 544; r += 512) {
            int hl  = r / 136;
            int tok = r - hl * 136;
            int tl  = tok / 17;
            int n   = tok - tl * 17;
            const float* qp = qsf + tok * 36 + hl * 8;
            const float* kb = ksf + (tl * 17) * 36 + hl * 8;
            const float* vb = vsf + (tl * 17) * 36 + hl * 8;
            const float* mb = mbf + hl * 289 + n * 17;
            float4 q0 = *(const float4*)(qp);
            float4 q1 = *(const float4*)(qp + 4);
            float ev[17];
            float mx = -3.4e38f;
#pragma unroll
            for (int m = 0; m < 17; ++m) {
                const float* kp = kb + m * 36;
                float4 k0 = *(const float4*)(kp);
                float4 k1 = *(const float4*)(kp + 4);
                float d0 = q0.x * k0.x;
                d0 = fmaf(q0.y, k0.y, d0); d0 = fmaf(q0.z, k0.z, d0); d0 = fmaf(q0.w, k0.w, d0);
                d0 = fmaf(q1.x, k1.x, d0); d0 = fmaf(q1.y, k1.y, d0);
                d0 = fmaf(q1.z, k1.z, d0); d0 = fmaf(q1.w, k1.w, d0);
                ev[m] = fmaf(d0, inv_s, mb[m]);
                mx = fmaxf(mx, ev[m]);
            }
            float s = 0.f;
#pragma unroll
            for (int m = 0; m < 17; ++m) { ev[m] = __expf(ev[m] - mx); s += ev[m]; }
            float inv = __fdividef(1.0f, s);
            float a0x = 0.f, a0y = 0.f, a0z = 0.f, a0w = 0.f;
            float a1x = 0.f, a1y = 0.f, a1z = 0.f, a1w = 0.f;
#pragma unroll
            for (int m = 0; m < 17; ++m) {
                const float* vp = vb + m * 36;
                float4 v0 = *(const float4*)(vp);
                float4 v1 = *(const float4*)(vp + 4);
                float pm = ev[m];
                a0x = fmaf(pm, v0.x, a0x); a0y = fmaf(pm, v0.y, a0y);
                a0z = fmaf(pm, v0.z, a0z); a0w = fmaf(pm, v0.w, a0w);
                a1x = fmaf(pm, v1.x, a1x); a1y = fmaf(pm, v1.y, a1y);
                a1z = fmaf(pm, v1.z, a1z); a1w = fmaf(pm, v1.w, a1w);
            }
            u32 h0, l0, h1, l1, h2, l2, h3, l3;
            split2h(a0x * inv, a0y * inv, h0, l0);
            split2h(a0z * inv, a0w * inv, h1, l1);
            split2h(a1x * inv, a1y * inv, h2, l2);
            split2h(a1z * inv, a1w * inv, h3, l3);
            u32 off = (u32)tok * 528u + 256u + (u32)g * 64u + (u32)hl * 16u;
            *(uint4*)(sp + AH_B + off) = make_uint4(h0, h1, h2, h3);
            *(uint4*)(sp + AL_B + off) = make_uint4(l0, l1, l2, l3);
        }
    }

    // ---- Phase C: conv1x1 via MMA (K=256), 4 chunks of 64 outputs, direct STG ----
    const float* bnsc = (const float*)(sp + BNS_B);
    const float* bnsh = (const float*)(sp + BNB_B);
    const u32 CW = QS_B;                // conv weight stage: 33792 B, spans QS + part of KS
    for (int cb = 0; cb < 4; ++cb) {
        __syncthreads();   // prev stage ldsm reads done; attention reads done (cb=0)
        {
            const char* src = (const char*)&g_Bconv[cb][0];
            for (int j = tid; j < 2112; j += 512)
                cpasync16(sb + CW + (u32)j * 16u, src + (size_t)j * 16);
            asm volatile("cp.async.commit_group;" ::: "memory");
            asm volatile("cp.async.wait_group 0;" ::: "memory");
        }
        __syncthreads();   // weights visible to all

        // 18 units = (mt 0..8, nh 0..1); nh covers 4 n-tiles (32 outputs)
        for (int u = wid; u < 18; u += 16) {
            int mt = u >> 1, nh = u & 1;
            u32 abase = sb + AH_B + (u32)(mt * 16 + (lane & 15)) * 528u + (u32)((lane >> 4) * 16);
            u32 albase = abase + (AL_B - AH_B);
            u32 bb0 = sb + CW + (u32)(lane & 7) * 528u + (u32)(((lane >> 3) & 1) * 16);
            float c[4][4];
#pragma unroll
            for (int nt = 0; nt < 4; ++nt)
#pragma unroll
                for (int e = 0; e < 4; ++e) c[nt][e] = 0.f;
#pragma unroll 4
            for (int k = 0; k < 16; ++k) {
                u32 ah[4], al[4];
                ldsm4(ah, abase + (u32)k * 32u);
                ldsm4(al, albase + (u32)k * 32u);
#pragma unroll
                for (int nt = 0; nt < 4; ++nt) {
                    int ncol = nh * 4 + nt;
                    u32 bh[2];
                    ldsm2(bh, bb0 + (u32)(ncol * 8) * 528u + (u32)k * 32u);
                    mma16816(c[nt], ah, bh);
                    mma16816(c[nt], al, bh);
                }
            }
            // BN + ReLU + direct store
            int rlo = mt * 16 + row_lo0, rhi = rlo + 8;
#pragma unroll
            for (int nt = 0; nt < 4; ++nt) {
                int og = cb * 64 + nh * 32 + nt * 8 + col0;
                float s0 = bnsc[og], h0 = bnsh[og];
                float s1 = bnsc[og + 1], h1 = bnsh[og + 1];
                float* op0 = out + (size_t)(b * 256 + og) * 8704 + (size_t)t0 * 17;
                float* op1 = op0 + 8704;
                op0[rlo] = fmaxf(fmaf(c[nt][0], s0, h0), 0.0f);
                op1[rlo] = fmaxf(fmaf(c[nt][1], s1, h1), 0.0f);
                if (rhi < 136) {
                    op0[rhi] = fmaxf(fmaf(c[nt][2], s0, h0), 0.0f);
                    op1[rhi] = fmaxf(fmaf(c[nt][3], s1, h1), 0.0f);
                }
            }
        }
    }
}

// ---------------- launch ----------------
extern "C" void kernel_launch(void* const* d_in, const int* in_sizes, int n_in,
                              void* d_out, int out_size) {
    const float* x      = (const float*)d_in[0];
    const float* adj    = (const float*)d_in[1];
    const float* Wq     = (const float*)d_in[2];
    const float* Wk     = (const float*)d_in[3];
    const float* Wv     = (const float*)d_in[4];
    const float* adj2   = (const float*)d_in[5];
    const float* convw  = (const float*)d_in[6];
    const float* bng    = (const float*)d_in[7];
    const float* bnb    = (const float*)d_in[8];
    const float* bnm    = (const float*)d_in[9];
    const float* bnv    = (const float*)d_in[10];
    float* out = (float*)d_out;

    cudaFuncSetAttribute(gab_kernel, cudaFuncAttributeMaxDynamicSharedMemorySize, SMEM_BYTES);

    prep_kernel<<<(4 * 96 * 128 + 256 * 256 + 255) / 256, 256>>>(Wq, Wk, Wv, convw);
    gab_kernel<<<2048, 512, SMEM_BYTES>>>(x, adj, adj2, bng, bnb, bnm, bnv, out);
}

// round 16
// speedup vs baseline: 2.7945x; 1.0381x over previous
#include <cuda_runtime.h>
#include <cuda_fp16.h>
#include <cstdint>
#include <cstddef>

typedef unsigned int u32;

#define NEG_INFF (-9.0e15f)
#define BN_EPS 1e-5f

// ---------------- smem layout (bytes) ----------------
// A tiles: [136 tok][264 k] fp16, stride 528 B (ldmatrix conflict-free: 33%8==1)
#define AH_B   0u
#define AL_B   71808u          // 136*528
#define QS_B   143616u         // qs[136][36] f32 ; ALSO: qkv B-stage (26112 B) / conv weights (33792 B)
#define KS_B   163200u
#define VS_B   182784u
#define MB_B   202368u         // mask 4*289 f32 = 4624
#define BNS_B  224400u         // bn scale 256 f32
#define BNB_B  225424u
#define SMEM_BYTES 226448u

// ---------------- pre-packed fp16 weight images ----------------
// g_Bqkv[g][n*136+c]: n = third*32+nl (q:0-31, k:32-63, v:64-95), k-stride 136 halves (272 B rows)
__device__ __align__(16) __half g_Bqkv[4][96 * 136];
// g_Bconv[cb][n*264+c]: 4 chunks of 64 outputs, k-stride 264 halves (528 B rows), K=256
__device__ __align__(16) __half g_Bconv[4][64 * 264];

__global__ void prep_kernel(const float* __restrict__ Wq, const float* __restrict__ Wk,
                            const float* __restrict__ Wv, const float* __restrict__ cw) {
    int i = blockIdx.x * blockDim.x + threadIdx.x;
    if (i < 4 * 96 * 128) {
        int g = i / 12288; int r = i - g * 12288;
        int n = r >> 7, c = r & 127;
        int third = n >> 5, nl = n & 31;
        int h = g * 4 + (nl >> 3), e = nl & 7;
        const float* W = (third == 0) ? Wq : (third == 1 ? Wk : Wv);
        float w = W[h * 1024 + c * 8 + e];        // W[h][c][e] (16,128,8)
        g_Bqkv[g][n * 136 + c] = __float2half_rn(w);
    } else {
        int j = i - 4 * 96 * 128;
        if (j < 256 * 256) {
            int o = j >> 8, c = j & 255;
            int cb = o >> 6, n = o & 63;
            g_Bconv[cb][n * 264 + c] = __float2half_rn(cw[o * 256 + c]);
        }
    }
}

// ---------------- warp mma helpers ----------------
__device__ __forceinline__ u32 smem_u32(const void* p) {
    u32 a;
    asm("{ .reg .u64 t; cvta.to.shared.u64 t, %1; cvt.u32.u64 %0, t; }" : "=r"(a) : "l"(p));
    return a;
}
__device__ __forceinline__ void ldsm4(u32* r, u32 a) {
    asm volatile("ldmatrix.sync.aligned.m8n8.x4.shared.b16 {%0,%1,%2,%3}, [%4];"
                 : "=r"(r[0]), "=r"(r[1]), "=r"(r[2]), "=r"(r[3]) : "r"(a));
}
__device__ __forceinline__ void ldsm2(u32* r, u32 a) {
    asm volatile("ldmatrix.sync.aligned.m8n8.x2.shared.b16 {%0,%1}, [%2];"
                 : "=r"(r[0]), "=r"(r[1]) : "r"(a));
}
__device__ __forceinline__ void mma16816(float* c, const u32* a, const u32* b) {
    asm volatile(
        "mma.sync.aligned.m16n8k16.row.col.f32.f16.f16.f32 "
        "{%0,%1,%2,%3}, {%4,%5,%6,%7}, {%8,%9}, {%0,%1,%2,%3};"
        : "+f"(c[0]), "+f"(c[1]), "+f"(c[2]), "+f"(c[3])
        : "r"(a[0]), "r"(a[1]), "r"(a[2]), "r"(a[3]), "r"(b[0]), "r"(b[1]));
}
// split two floats into fp16 hi and fp16 residual (packed as half2 words)
__device__ __forceinline__ void split2h(float a, float b, u32& hu, u32& lu) {
    __half ha = __float2half_rn(a), hb = __float2half_rn(b);
    float ra = a - __half2float(ha), rb = b - __half2float(hb);
    __half la = __float2half_rn(ra), lb = __float2half_rn(rb);
    hu = (u32)__half_as_ushort(ha) | ((u32)__half_as_ushort(hb) << 16);
    lu = (u32)__half_as_ushort(la) | ((u32)__half_as_ushort(lb) << 16);
}
__device__ __forceinline__ void cpasync16(u32 dst, const void* src) {
    unsigned long long g;
    asm("cvta.to.global.u64 %0, %1;" : "=l"(g) : "l"(src));
    asm volatile("cp.async.cg.shared.global [%0], [%1], 16;" :: "r"(dst), "l"(g) : "memory");
}

extern __shared__ __align__(16) unsigned char sp[];

__global__ void __launch_bounds__(512, 1)
gab_kernel(const float* __restrict__ x, const float* __restrict__ adj,
           const float* __restrict__ adj2,
           const float* __restrict__ bng, const float* __restrict__ bnbv,
           const float* __restrict__ bnm, const float* __restrict__ bnv,
           float* __restrict__ out) {
    const u32 sb = smem_u32(sp);
    const int b  = blockIdx.x >> 6;
    const int tb = blockIdx.x & 63;
    const int t0 = tb * 8;
    const int tid  = threadIdx.x;
    const int lane = tid & 31;
    const int wid  = tid >> 5;

    // ---- Phase A: load X, fp16-split into A_hi/A_lo [tok][c] (c: 0..127) ----
    {
        const float* xb = x + (size_t)b * 128 * 8704 + (size_t)t0 * 17;
        for (int d4 = wid; d4 < 32; d4 += 16) {
            const float* s0 = xb + (size_t)(d4 * 4 + 0) * 8704;
            const float* s1 = xb + (size_t)(d4 * 4 + 1) * 8704;
            const float* s2 = xb + (size_t)(d4 * 4 + 2) * 8704;
            const float* s3 = xb + (size_t)(d4 * 4 + 3) * 8704;
            for (int tok = lane; tok < 136; tok += 32) {
                float v0 = s0[tok], v1 = s1[tok], v2 = s2[tok], v3 = s3[tok];
                u32 h01, l01, h23, l23;
                split2h(v0, v1, h01, l01);
                split2h(v2, v3, h23, l23);
                u32 off = (u32)tok * 528u + (u32)d4 * 8u;
                *(uint2*)(sp + AH_B + off) = make_uint2(h01, h23);
                *(uint2*)(sp + AL_B + off) = make_uint2(l01, l23);
            }
        }
    }
    // ---- BN fold ----
    if (tid < 256) {
        float sc = bng[tid] * rsqrtf(bnv[tid] + BN_EPS);
        ((float*)(sp + BNS_B))[tid] = sc;
        ((float*)(sp + BNB_B))[tid] = bnbv[tid] - bnm[tid] * sc;
    }

    const float inv_s = 0.3535533905932738f;   // 1/sqrt(8)
    float* qsf = (float*)(sp + QS_B);
    float* ksf = (float*)(sp + KS_B);
    float* vsf = (float*)(sp + VS_B);
    float* mbf = (float*)(sp + MB_B);
    const int row_lo0 = (lane >> 2);
    const int col0 = (lane & 3) * 2;

    // ---- Phase B: 4 head-groups; per group: ONE merged qkv stage, then attention ----
    for (int g = 0; g < 4; ++g) {
        __syncthreads();   // prev-group attention / Phase A reads+writes complete; qs region dead
        // stage merged B (96 cols x 128 k = 26112 B) into QS region via cp.async
        {
            const char* src = (const char*)&g_Bqkv[g][0];
            for (int j = tid; j < 1632; j += 512)
                cpasync16(sb + QS_B + (u32)j * 16u, src + (size_t)j * 16);
            asm volatile("cp.async.commit_group;" ::: "memory");
            asm volatile("cp.async.wait_group 0;" ::: "memory");
        }
        // mask bias for this group
        for (int idx = tid; idx < 4 * 289; idx += 512) {
            int hl = idx / 289, r = idx - hl * 289;
            int n = r / 17, m = r - n * 17;
            int hh = g * 4 + hl;
            float a = 0.5f * (adj[n * 17 + m] + adj[m * 17 + n])
                    + 0.5f * (adj2[hh * 289 + n * 17 + m] + adj2[hh * 289 + m * 17 + n]);
            mbf[idx] = (a > 0.0f) ? 0.0f : NEG_INFF;
        }
        __syncthreads();   // B + mask visible

        // mainloop: unit = (mt, nh); nh covers 6 ncols of 12 (q:0-3, k:4-7, v:8-11)
        auto run_unit = [&](int u, float (*c)[4]) {
            int mt = u >> 1, nh = u & 1;
            u32 abase = sb + AH_B + (u32)(mt * 16 + (lane & 15)) * 528u + (u32)((lane >> 4) * 16);
            u32 albase = abase + (AL_B - AH_B);
            u32 bbase = sb + QS_B + (u32)(lane & 7) * 272u + (u32)(((lane >> 3) & 1) * 16)
                      + (u32)(nh * 6 * 8) * 272u;
#pragma unroll
            for (int nt = 0; nt < 6; ++nt)
#pragma unroll
                for (int e = 0; e < 4; ++e) c[nt][e] = 0.f;
#pragma unroll
            for (int k = 0; k < 8; ++k) {
                u32 ah[4], al[4];
                ldsm4(ah, abase + (u32)k * 32u);
                ldsm4(al, albase + (u32)k * 32u);
#pragma unroll
                for (int nt = 0; nt < 6; ++nt) {
                    u32 bh[2];
                    ldsm2(bh, bbase + (u32)(nt * 8) * 272u + (u32)k * 32u);
                    mma16816(c[nt], ah, bh);
                    mma16816(c[nt], al, bh);
                }
            }
        };
        auto store_unit = [&](int u, float (*c)[4]) {
            int mt = u >> 1, nh = u & 1;
            int rlo = mt * 16 + row_lo0, rhi = rlo + 8;
#pragma unroll
            for (int nt = 0; nt < 6; ++nt) {
                int ncol = nh * 6 + nt;
                float* bufp; int oc;
                if (ncol < 4)      { bufp = qsf; oc = ncol * 8 + col0; }
                else if (ncol < 8) { bufp = ksf; oc = (ncol - 4) * 8 + col0; }
                else               { bufp = vsf; oc = (ncol - 8) * 8 + col0; }
                *(float2*)(bufp + rlo * 36 + oc) = make_float2(c[nt][0], c[nt][1]);
                if (rhi < 136)
                    *(float2*)(bufp + rhi * 36 + oc) = make_float2(c[nt][2], c[nt][3]);
            }
        };

        float c0[6][4];
        run_unit(wid, c0);
        float c1[6][4];
        if (wid < 2) run_unit(wid + 16, c1);
        __syncthreads();   // ALL B-stage reads complete before qs/ks/vs overwrite the region
        store_unit(wid, c0);
        if (wid < 2) store_unit(wid + 16, c1);
        __syncthreads();   // q/k/v visible

        // ---- attention: 32 tasks = (tl 0..7, hl 0..3); lanes 0..16 = query joint n ----
        for (int t = wid; t < 32; t += 16) {
            int tl = t >> 2;
            int hl = t & 3;
            int tok = tl * 17 + lane;              // valid for lane<17
            bool act = lane < 17;
            const float* kb = ksf + (tl * 17) * 36 + hl * 8;   // warp-uniform (broadcast loads)
            const float* vb = vsf + (tl * 17) * 36 + hl * 8;
            const float* qp = qsf + tok * 36 + hl * 8;
            const float* mb = mbf + hl * 289 + lane * 17;
            float4 q0 = *(const float4*)(qp);
            float4 q1 = *(const float4*)(qp + 4);
            float ev[17];
            float mx = -3.4e38f;
#pragma unroll
            for (int m = 0; m < 17; ++m) {
                const float* kp = kb + m * 36;
                float4 k0 = *(const float4*)(kp);
                float4 k1 = *(const float4*)(kp + 4);
                float d0 = q0.x * k0.x;
                d0 = fmaf(q0.y, k0.y, d0); d0 = fmaf(q0.z, k0.z, d0); d0 = fmaf(q0.w, k0.w, d0);
                d0 = fmaf(q1.x, k1.x, d0); d0 = fmaf(q1.y, k1.y, d0);
                d0 = fmaf(q1.z, k1.z, d0); d0 = fmaf(q1.w, k1.w, d0);
                ev[m] = fmaf(d0, inv_s, mb[m]);
                mx = fmaxf(mx, ev[m]);
            }
            float s = 0.f;
#pragma unroll
            for (int m = 0; m < 17; ++m) { ev[m] = __expf(ev[m] - mx); s += ev[m]; }
            float inv = __fdividef(1.0f, s);
            float a0x = 0.f, a0y = 0.f, a0z = 0.f, a0w = 0.f;
            float a1x = 0.f, a1y = 0.f, a1z = 0.f, a1w = 0.f;
#pragma unroll
            for (int m = 0; m < 17; ++m) {
                const float* vp = vb + m * 36;
                float4 v0 = *(const float4*)(vp);
                float4 v1 = *(const float4*)(vp + 4);
                float pm = ev[m];
                a0x = fmaf(pm, v0.x, a0x); a0y = fmaf(pm, v0.y, a0y);
                a0z = fmaf(pm, v0.z, a0z); a0w = fmaf(pm, v0.w, a0w);
                a1x = fmaf(pm, v1.x, a1x); a1y = fmaf(pm, v1.y, a1y);
                a1z = fmaf(pm, v1.z, a1z); a1w = fmaf(pm, v1.w, a1w);
            }
            if (act) {
                u32 h0, l0, h1, l1, h2, l2, h3, l3;
                split2h(a0x * inv, a0y * inv, h0, l0);
                split2h(a0z * inv, a0w * inv, h1, l1);
                split2h(a1x * inv, a1y * inv, h2, l2);
                split2h(a1z * inv, a1w * inv, h3, l3);
                u32 off = (u32)tok * 528u + 256u + (u32)g * 64u + (u32)hl * 16u;
                *(uint4*)(sp + AH_B + off) = make_uint4(h0, h1, h2, h3);
                *(uint4*)(sp + AL_B + off) = make_uint4(l0, l1, l2, l3);
            }
        }
    }

    // ---- Phase C: conv1x1 via MMA (K=256), 4 chunks of 64 outputs, direct STG ----
    const float* bnsc = (const float*)(sp + BNS_B);
    const float* bnsh = (const float*)(sp + BNB_B);
    const u32 CW = QS_B;                // conv weight stage: 33792 B, spans QS + part of KS
    for (int cb = 0; cb < 4; ++cb) {
        __syncthreads();   // prev stage ldsm reads done; attention writes visible (cb=0)
        {
            const char* src = (const char*)&g_Bconv[cb][0];
            for (int j = tid; j < 2112; j += 512)
                cpasync16(sb + CW + (u32)j * 16u, src + (size_t)j * 16);
            asm volatile("cp.async.commit_group;" ::: "memory");
            asm volatile("cp.async.wait_group 0;" ::: "memory");
        }
        __syncthreads();   // weights visible to all

        // 18 units = (mt 0..8, nh 0..1); nh covers 4 n-tiles (32 outputs)
        for (int u = wid; u < 18; u += 16) {
            int mt = u >> 1, nh = u & 1;
            u32 abase = sb + AH_B + (u32)(mt * 16 + (lane & 15)) * 528u + (u32)((lane >> 4) * 16);
            u32 albase = abase + (AL_B - AH_B);
            u32 bb0 = sb + CW + (u32)(lane & 7) * 528u + (u32)(((lane >> 3) & 1) * 16);
            float c[4][4];
#pragma unroll
            for (int nt = 0; nt < 4; ++nt)
#pragma unroll
                for (int e = 0; e < 4; ++e) c[nt][e] = 0.f;
#pragma unroll 4
            for (int k = 0; k < 16; ++k) {
                u32 ah[4], al[4];
                ldsm4(ah, abase + (u32)k * 32u);
                ldsm4(al, albase + (u32)k * 32u);
#pragma unroll
                for (int nt = 0; nt < 4; ++nt) {
                    int ncol = nh * 4 + nt;
                    u32 bh[2];
                    ldsm2(bh, bb0 + (u32)(ncol * 8) * 528u + (u32)k * 32u);
                    mma16816(c[nt], ah, bh);
                    mma16816(c[nt], al, bh);
                }
            }
            // BN + ReLU + direct store
            int rlo = mt * 16 + row_lo0, rhi = rlo + 8;
#pragma unroll
            for (int nt = 0; nt < 4; ++nt) {
                int og = cb * 64 + nh * 32 + nt * 8 + col0;
                float s0 = bnsc[og], h0 = bnsh[og];
                float s1 = bnsc[og + 1], h1 = bnsh[og + 1];
                float* op0 = out + (size_t)(b * 256 + og) * 8704 + (size_t)t0 * 17;
                float* op1 = op0 + 8704;
                op0[rlo] = fmaxf(fmaf(c[nt][0], s0, h0), 0.0f);
                op1[rlo] = fmaxf(fmaf(c[nt][1], s1, h1), 0.0f);
                if (rhi < 136) {
                    op0[rhi] = fmaxf(fmaf(c[nt][2], s0, h0), 0.0f);
                    op1[rhi] = fmaxf(fmaf(c[nt][3], s1, h1), 0.0f);
                }
            }
        }
    }
}

// ---------------- launch ----------------
extern "C" void kernel_launch(void* const* d_in, const int* in_sizes, int n_in,
                              void* d_out, int out_size) {
    const float* x      = (const float*)d_in[0];
    const float* adj    = (const float*)d_in[1];
    const float* Wq     = (const float*)d_in[2];
    const float* Wk     = (const float*)d_in[3];
    const float* Wv     = (const float*)d_in[4];
    const float* adj2   = (const float*)d_in[5];
    const float* convw  = (const float*)d_in[6];
    const float* bng    = (const float*)d_in[7];
    const float* bnb    = (const float*)d_in[8];
    const float* bnm    = (const float*)d_in[9];
    const float* bnv    = (const float*)d_in[10];
    float* out = (float*)d_out;

    cudaFuncSetAttribute(gab_kernel, cudaFuncAttributeMaxDynamicSharedMemorySize, SMEM_BYTES);

    prep_kernel<<<(4 * 96 * 128 + 256 * 256 + 255) / 256, 256>>>(Wq, Wk, Wv, convw);
    gab_kernel<<<2048, 512, SMEM_BYTES>>>(x, adj, adj2, bng, bnb, bnm, bnv, out);
}